// round 12
// baseline (speedup 1.0000x reference)
#include <cuda_runtime.h>
#include <cuda_fp16.h>
#include <cstdint>

// Problem constants
#define Bn  4
#define Nn  2048
#define Dn  512
#define Hn  8
#define HDn 64
#define MT  (Bn*Nn)   // 8192 rows

// Scratch (allocation-free rule: __device__ globals) — fp16 hi/lo splits
__device__ __half g_xh[MT*Dn], g_xl[MT*Dn];           // input q split
__device__ __half g_wh[4*Dn*Dn], g_wl[4*Dn*Dn];       // Wq,Wk,Wv,Wo split
__device__ __half g_qh[MT*Dn], g_ql[MT*Dn];           // Q proj (scaled 1/8)
__device__ __half g_kh[MT*Dn], g_kl[MT*Dn];           // K proj [tok][dim]
__device__ __half g_vth[MT*Dn], g_vtl[MT*Dn];         // V proj transposed [(b,h,d)][tok]
__device__ __half g_oh[MT*Dn], g_ol[MT*Dn];           // attention output split
__device__ float g_maskf[Bn*Nn];

// ===========================================================================
// common helpers
// ===========================================================================
__device__ __forceinline__ uint32_t smem_u32(const void* p) {
    uint32_t a;
    asm("{ .reg .u64 t; cvta.to.shared.u64 t, %1; cvt.u32.u64 %0, t; }" : "=r"(a) : "l"(p));
    return a;
}
// fp16 operands, fp32 accumulate (hi*hi main term)
__device__ __forceinline__ void mma_f32acc(float* c, const uint32_t* a, const uint32_t* b) {
    asm volatile("mma.sync.aligned.m16n8k16.row.col.f32.f16.f16.f32 "
        "{%0,%1,%2,%3}, {%4,%5,%6,%7}, {%8,%9}, {%0,%1,%2,%3};"
        : "+f"(c[0]), "+f"(c[1]), "+f"(c[2]), "+f"(c[3])
        : "r"(a[0]), "r"(a[1]), "r"(a[2]), "r"(a[3]), "r"(b[0]), "r"(b[1]));
}
// fp16 operands, fp16 accumulate (correction terms — possibly double-rate)
__device__ __forceinline__ void mma_f16acc(uint32_t* d, const uint32_t* a, const uint32_t* b) {
    asm volatile("mma.sync.aligned.m16n8k16.row.col.f16.f16.f16.f16 "
        "{%0,%1}, {%2,%3,%4,%5}, {%6,%7}, {%0,%1};"
        : "+r"(d[0]), "+r"(d[1])
        : "r"(a[0]), "r"(a[1]), "r"(a[2]), "r"(a[3]), "r"(b[0]), "r"(b[1]));
}
__device__ __forceinline__ void merge_corr(float* c, const uint32_t* d) {
    __half2 p0 = *reinterpret_cast<const __half2*>(&d[0]);
    __half2 p1 = *reinterpret_cast<const __half2*>(&d[1]);
    c[0] += __low2float(p0); c[1] += __high2float(p0);
    c[2] += __low2float(p1); c[3] += __high2float(p1);
}
__device__ __forceinline__ void ldm_x4(uint32_t* r, uint32_t saddr) {
    asm volatile("ldmatrix.sync.aligned.m8n8.x4.shared.b16 {%0,%1,%2,%3}, [%4];"
        : "=r"(r[0]), "=r"(r[1]), "=r"(r[2]), "=r"(r[3]) : "r"(saddr));
}
__device__ __forceinline__ void cp16(uint32_t saddr, const void* g) {
    asm volatile("cp.async.ca.shared.global [%0], [%1], 16;" :: "r"(saddr), "l"(g));
}
__device__ __forceinline__ void cp_commit() { asm volatile("cp.async.commit_group;" ::: "memory"); }
__device__ __forceinline__ void cp_wait0()  { asm volatile("cp.async.wait_group 0;" ::: "memory"); }
__device__ __forceinline__ void cp_wait1()  { asm volatile("cp.async.wait_group 1;" ::: "memory"); }

__device__ __forceinline__ uint32_t packh_hi(float x, float y, float& rx, float& ry) {
    __half hx = __float2half_rn(x), hy = __float2half_rn(y);
    rx = x - __half2float(hx);
    ry = y - __half2float(hy);
    return (uint32_t)__half_as_ushort(hx) | ((uint32_t)__half_as_ushort(hy) << 16);
}
__device__ __forceinline__ uint32_t packh(float x, float y) {
    return (uint32_t)__half_as_ushort(__float2half_rn(x)) |
           ((uint32_t)__half_as_ushort(__float2half_rn(y)) << 16);
}
__device__ __forceinline__ void packhl(float x, float y, uint32_t& h, uint32_t& l) {
    float rx, ry;
    h = packh_hi(x, y, rx, ry);
    l = packh(rx, ry);
}

// ===========================================================================
// prep: mask -> float addend; fp32 -> fp16 hi/lo split
// ===========================================================================
__global__ void mask_prep(const int* __restrict__ mask) {
    int i = blockIdx.x * blockDim.x + threadIdx.x;
    if (i < Bn * Nn) g_maskf[i] = mask[i] ? -1e30f : 0.0f;
}

__global__ void prep_split_x(const float4* __restrict__ src) {
    int i = blockIdx.x * blockDim.x + threadIdx.x;      // over MT*Dn/4
    float4 v = src[i];
    float r0, r1, r2, r3;
    uint32_t h0 = packh_hi(v.x, v.y, r0, r1);
    uint32_t h1 = packh_hi(v.z, v.w, r2, r3);
    reinterpret_cast<uint2*>(g_xh)[i] = make_uint2(h0, h1);
    reinterpret_cast<uint2*>(g_xl)[i] = make_uint2(packh(r0, r1), packh(r2, r3));
}

__global__ void prep_split_w(const float4* __restrict__ w0, const float4* __restrict__ w1,
                             const float4* __restrict__ w2, const float4* __restrict__ w3) {
    int i = blockIdx.x * blockDim.x + threadIdx.x;      // over Dn*Dn/4
    int z = blockIdx.y;
    const float4* src = (z == 0) ? w0 : (z == 1) ? w1 : (z == 2) ? w2 : w3;
    float4 v = src[i];
    float r0, r1, r2, r3;
    uint32_t h0 = packh_hi(v.x, v.y, r0, r1);
    uint32_t h1 = packh_hi(v.z, v.w, r2, r3);
    size_t o = (size_t)z * (Dn * Dn / 4) + i;
    reinterpret_cast<uint2*>(g_wh)[o] = make_uint2(h0, h1);
    reinterpret_cast<uint2*>(g_wl)[o] = make_uint2(packh(r0, r1), packh(r2, r3));
}

// ===========================================================================
// fp16x3 GEMM: CTA tile 256x128, 8 warps as 4(m) x 2(n), warp tile 64x64.
// BK=32, 2-stage cp.async, ldmatrix. hi*hi -> f32 acc; hl+lh -> f16 acc.
// ===========================================================================
#define BK    32
#define SAstr 40                    // fp16 elems per smem row (80 B)
#define GA_AH 0
#define GA_AL 20480                 // 256*80
#define GA_BH 40960
#define GA_BL 51200                 // +128*80
#define GSTG  61440
#define SMEM_GEMM (2*GSTG)          // 122880 B
#define NCH   (Dn/BK)               // 16

#define GEMM_MAINLOOP(AH, AL, BH, BL, ACC, CACC) \
    const uint32_t sU = smem_u32(smg); \
    const __half* Ah_g = (AH) + (size_t)m0 * Dn; \
    const __half* Al_g = (AL) + (size_t)m0 * Dn; \
    const __half* Bh_g = (BH) + (size_t)n0 * Dn; \
    const __half* Bl_g = (BL) + (size_t)n0 * Dn; \
    auto prefetch = [&](int kc) { \
        const uint32_t u = sU + (kc & 1) * GSTG; \
        _Pragma("unroll") \
        for (int t = 0; t < 4; t++) {                /* A: 256 rows x 4 chunks */ \
            int id = tid + t * 256; \
            int row = id >> 2, c = id & 3; \
            size_t go = (size_t)row * Dn + kc * BK + c * 8; \
            uint32_t so = u + row * (SAstr * 2) + c * 16; \
            cp16(so + GA_AH, Ah_g + go); \
            cp16(so + GA_AL, Al_g + go); \
        } \
        _Pragma("unroll") \
        for (int t = 0; t < 2; t++) {                /* B: 128 rows x 4 chunks */ \
            int id = tid + t * 256; \
            int row = id >> 2, c = id & 3; \
            size_t go = (size_t)row * Dn + kc * BK + c * 8; \
            uint32_t so = u + row * (SAstr * 2) + c * 16; \
            cp16(so + GA_BH, Bh_g + go); \
            cp16(so + GA_BL, Bl_g + go); \
        } \
        cp_commit(); \
    }; \
    prefetch(0); \
    _Pragma("unroll 1") \
    for (int kc = 0; kc < NCH; kc++) { \
        if (kc + 1 < NCH) { prefetch(kc + 1); cp_wait1(); } else { cp_wait0(); } \
        __syncthreads(); \
        const uint32_t s = sU + (kc & 1) * GSTG; \
        _Pragma("unroll") \
        for (int ks = 0; ks < 2; ks++) { \
            const int k0 = ks * 16; \
            uint32_t ah[4][4], al[4][4]; \
            _Pragma("unroll") \
            for (int t = 0; t < 4; t++) { \
                uint32_t ra = wm + t * 16 + (lane & 15); \
                uint32_t ad = s + (ra * SAstr + k0 + (lane >> 4) * 8) * 2; \
                ldm_x4(ah[t], ad + GA_AH); \
                ldm_x4(al[t], ad + GA_AL); \
            } \
            _Pragma("unroll") \
            for (int jj = 0; jj < 4; jj++) { \
                uint32_t rb = wn + 8 * (2 * jj + ((lane >> 4) & 1)) + (lane & 7); \
                uint32_t ad = s + (rb * SAstr + k0 + ((lane >> 3) & 1) * 8) * 2; \
                uint32_t bh[4], bl[4]; \
                ldm_x4(bh, ad + GA_BH); \
                ldm_x4(bl, ad + GA_BL); \
                _Pragma("unroll") \
                for (int t = 0; t < 4; t++) { \
                    mma_f32acc(ACC[t][2 * jj],      ah[t], &bh[0]); \
                    mma_f16acc(CACC[t][2 * jj],     ah[t], &bl[0]); \
                    mma_f16acc(CACC[t][2 * jj],     al[t], &bh[0]); \
                    mma_f32acc(ACC[t][2 * jj + 1],  ah[t], &bh[2]); \
                    mma_f16acc(CACC[t][2 * jj + 1], ah[t], &bl[2]); \
                    mma_f16acc(CACC[t][2 * jj + 1], al[t], &bh[2]); \
                } \
            } \
        } \
        __syncthreads(); \
    } \
    _Pragma("unroll") \
    for (int t = 0; t < 4; t++) \
        _Pragma("unroll") \
        for (int j = 0; j < 8; j++) merge_corr(ACC[t][j], CACC[t][j]);

// ---------------------------------------------------------------------------
// QKV projection GEMM: z=0 Q (scaled 1/8), z=1 K, z=2 V (smem-transposed)
// ---------------------------------------------------------------------------
#define TSTR2 264    // V-transpose smem: tokens per d-row (528 B, 16B-mult)

__global__ __launch_bounds__(256, 1) void gemm_qkv() {
    extern __shared__ __align__(16) char smg[];
    const int tid  = threadIdx.x;
    const int lane = tid & 31;
    const int g    = lane >> 2;
    const int tg   = lane & 3;
    const int wid  = tid >> 5;
    const int n0 = blockIdx.x * 128, m0 = blockIdx.y * 256;
    const int z  = blockIdx.z;
    const int wm = (wid & 3) * 64;     // 4 warps along M (256)
    const int wn = (wid >> 2) * 64;    // 2 warps along N (128)

    float acc[4][8][4];
    uint32_t cacc[4][8][2];
    #pragma unroll
    for (int t = 0; t < 4; t++)
        #pragma unroll
        for (int j = 0; j < 8; j++) {
            cacc[t][j][0] = 0u; cacc[t][j][1] = 0u;
            #pragma unroll
            for (int e = 0; e < 4; e++) acc[t][j][e] = 0.0f;
        }

    const __half* Wh = g_wh + (size_t)z * Dn * Dn;
    const __half* Wl = g_wl + (size_t)z * Dn * Dn;
    GEMM_MAINLOOP(g_xh, g_xl, Wh, Wl, acc, cacc)

    if (z < 2) {
        __half* Oh = (z == 0) ? g_qh : g_kh;
        __half* Ol = (z == 0) ? g_ql : g_kl;
        const float sc = (z == 0) ? 0.125f : 1.0f;
        #pragma unroll
        for (int t = 0; t < 4; t++)
            #pragma unroll
            for (int j = 0; j < 8; j++) {
                int r = m0 + wm + t * 16 + g;
                int c = n0 + wn + j * 8 + tg * 2;
                float v0 = acc[t][j][0] * sc, v1 = acc[t][j][1] * sc;
                float v2 = acc[t][j][2] * sc, v3 = acc[t][j][3] * sc;
                uint32_t h, l;
                packhl(v0, v1, h, l);
                *reinterpret_cast<uint32_t*>(&Oh[(size_t)r * Dn + c]) = h;
                *reinterpret_cast<uint32_t*>(&Ol[(size_t)r * Dn + c]) = l;
                packhl(v2, v3, h, l);
                *reinterpret_cast<uint32_t*>(&Oh[(size_t)(r + 8) * Dn + c]) = h;
                *reinterpret_cast<uint32_t*>(&Ol[(size_t)(r + 8) * Dn + c]) = l;
            }
    } else {
        // V: transpose through smem in two passes (hi then lo), coalesced out
        #pragma unroll
        for (int pass = 0; pass < 2; pass++) {
            __syncthreads();
            #pragma unroll
            for (int t = 0; t < 4; t++)
                #pragma unroll
                for (int j = 0; j < 8; j++)
                    #pragma unroll
                    for (int e = 0; e < 4; e++) {
                        int lr = wm + t * 16 + g + (e >> 1) * 8;   // local token 0..255
                        int lc = wn + j * 8 + tg * 2 + (e & 1);    // local dim 0..127
                        float v = acc[t][j][e];
                        __half hv = __float2half_rn(v);
                        __half sv = pass ? __float2half_rn(v - __half2float(hv)) : hv;
                        *reinterpret_cast<__half*>(smg + (size_t)lc * (TSTR2 * 2) + lr * 2) = sv;
                    }
            __syncthreads();
            const int dd = tid >> 1;          // 0..127 (local dim)
            const int hf = tid & 1;           // token half (128 each)
            const int b  = m0 >> 11;
            const int hh = (n0 + dd) >> 6;
            const int d  = (n0 + dd) & 63;
            __half* dstp = pass ? g_vtl : g_vth;
            const size_t dst = (((size_t)(b * Hn + hh)) * HDn + d) * Nn + (m0 & (Nn - 1)) + hf * 128;
            const uint32_t so = (uint32_t)dd * (TSTR2 * 2) + hf * 256;
            #pragma unroll
            for (int u = 0; u < 16; u++)
                *reinterpret_cast<uint4*>(&dstp[dst + u * 8]) =
                    *reinterpret_cast<const uint4*>(smg + so + u * 16);
        }
    }
}

// ---------------------------------------------------------------------------
// Output projection GEMM: reads pre-split O, writes fp32
// ---------------------------------------------------------------------------
__global__ __launch_bounds__(256, 1) void gemm_out(float* __restrict__ C) {
    extern __shared__ __align__(16) char smg[];
    const int tid  = threadIdx.x;
    const int lane = tid & 31;
    const int g    = lane >> 2;
    const int tg   = lane & 3;
    const int wid  = tid >> 5;
    const int n0 = blockIdx.x * 128, m0 = blockIdx.y * 256;
    const int wm = (wid & 3) * 64;
    const int wn = (wid >> 2) * 64;

    float acc[4][8][4];
    uint32_t cacc[4][8][2];
    #pragma unroll
    for (int t = 0; t < 4; t++)
        #pragma unroll
        for (int j = 0; j < 8; j++) {
            cacc[t][j][0] = 0u; cacc[t][j][1] = 0u;
            #pragma unroll
            for (int e = 0; e < 4; e++) acc[t][j][e] = 0.0f;
        }

    const __half* Wh = g_wh + (size_t)3 * Dn * Dn;
    const __half* Wl = g_wl + (size_t)3 * Dn * Dn;
    GEMM_MAINLOOP(g_oh, g_ol, Wh, Wl, acc, cacc)

    #pragma unroll
    for (int t = 0; t < 4; t++)
        #pragma unroll
        for (int j = 0; j < 8; j++) {
            int row = m0 + wm + t * 16 + g;
            int col = n0 + wn + j * 8 + tg * 2;
            *reinterpret_cast<float2*>(C + (size_t)row * Dn + col) =
                make_float2(acc[t][j][0], acc[t][j][1]);
            *reinterpret_cast<float2*>(C + (size_t)(row + 8) * Dn + col) =
                make_float2(acc[t][j][2], acc[t][j][3]);
        }
}

// ===========================================================================
// Tensor-core flash attention: 128 q-rows per CTA (8 warps x 16 rows),
// k-tiles of 64 keys, fp16x3 (hh f32-acc, corrections f16-acc),
// cp.async double buffer, 2 CTAs/SM.
// ===========================================================================
#define KSTR 144
#define VSTR 144
#define KARR (64*KSTR)
#define VARR (64*VSTR)
#define VOFF (2*KARR)
#define MOFF (2*KARR + 2*VARR)
#define STG_ATT (MOFF + 256)
#define SMEM_ATT (2*STG_ATT)

__global__ __launch_bounds__(256, 2) void attn_mma(const float* __restrict__ bias) {
    extern __shared__ __align__(16) char sma[];
    const uint32_t sb = smem_u32(sma);
    const int tid  = threadIdx.x;
    const int lane = tid & 31;
    const int w    = tid >> 5;
    const int g    = lane >> 2;
    const int tg   = lane & 3;
    const int h  = blockIdx.x;
    const int q0 = blockIdx.y * 128;
    const int b  = blockIdx.z;

    // ---- Q fragments from gmem (once) ----
    uint32_t qh[4][4], ql[4][4];
    {
        const size_t rbase = (size_t)(b * Nn + q0 + w * 16) * Dn + h * HDn;
        #pragma unroll
        for (int c = 0; c < 4; c++) {
            size_t o0 = rbase + (size_t)g * Dn + c * 16 + tg * 2;
            size_t o1 = rbase + (size_t)(g + 8) * Dn + c * 16 + tg * 2;
            qh[c][0] = *reinterpret_cast<const uint32_t*>(&g_qh[o0]);
            qh[c][1] = *reinterpret_cast<const uint32_t*>(&g_qh[o1]);
            qh[c][2] = *reinterpret_cast<const uint32_t*>(&g_qh[o0 + 8]);
            qh[c][3] = *reinterpret_cast<const uint32_t*>(&g_qh[o1 + 8]);
            ql[c][0] = *reinterpret_cast<const uint32_t*>(&g_ql[o0]);
            ql[c][1] = *reinterpret_cast<const uint32_t*>(&g_ql[o1]);
            ql[c][2] = *reinterpret_cast<const uint32_t*>(&g_ql[o0 + 8]);
            ql[c][3] = *reinterpret_cast<const uint32_t*>(&g_ql[o1 + 8]);
        }
    }

    const char* kh_base = (const char*)g_kh + ((size_t)(b * Nn) * Dn + h * HDn) * 2;
    const char* kl_base = (const char*)g_kl + ((size_t)(b * Nn) * Dn + h * HDn) * 2;
    const char* vh_base = (const char*)g_vth + ((size_t)(b * Hn + h) * HDn) * Nn * 2;
    const char* vl_base = (const char*)g_vtl + ((size_t)(b * Hn + h) * HDn) * Nn * 2;
    const char* mk_base = (const char*)g_maskf + (size_t)(b * Nn) * 4;

    auto prefetch = [&](int kt) {
        const uint32_t u = sb + (kt & 1) * STG_ATT;
        const size_t kof = (size_t)kt * 64 * (Dn * 2);
        #pragma unroll
        for (int t = 0; t < 2; t++) {
            int id = tid + t * 256;
            int row = id >> 3, c = id & 7;
            cp16(u + row * KSTR + c * 16,        kh_base + kof + (size_t)row * (Dn * 2) + c * 16);
            cp16(u + KARR + row * KSTR + c * 16, kl_base + kof + (size_t)row * (Dn * 2) + c * 16);
            cp16(u + VOFF + row * VSTR + c * 16,
                 vh_base + (size_t)row * (Nn * 2) + kt * 128 + c * 16);
            cp16(u + VOFF + VARR + row * VSTR + c * 16,
                 vl_base + (size_t)row * (Nn * 2) + kt * 128 + c * 16);
        }
        if (tid < 16) cp16(u + MOFF + tid * 16, mk_base + (size_t)kt * 256 + tid * 16);
        cp_commit();
    };

    float O[8][4];
    #pragma unroll
    for (int j = 0; j < 8; j++)
        #pragma unroll
        for (int e = 0; e < 4; e++) O[j][e] = 0.0f;
    float m0r = -3e38f, m1r = -3e38f, l0 = 0.0f, l1 = 0.0f;

    prefetch(0);

    const float* bb = bias + ((size_t)(b * Nn) + q0 + w * 16) * Nn;

    #pragma unroll 1
    for (int kt = 0; kt < Nn / 64; kt++) {
        cp_wait0();
        __syncthreads();
        const uint32_t u = sb + (kt & 1) * STG_ATT;
        if (kt + 1 < Nn / 64) prefetch(kt + 1);

        // ---- S = Q K^T (fp16x3: hh f32-acc, corrections f16-acc) ----
        float Sf[8][4];
        uint32_t Sc[8][2];
        #pragma unroll
        for (int j = 0; j < 8; j++) {
            Sc[j][0] = 0u; Sc[j][1] = 0u;
            #pragma unroll
            for (int e = 0; e < 4; e++) Sf[j][e] = 0.0f;
        }

        #pragma unroll
        for (int c = 0; c < 4; c++) {
            #pragma unroll
            for (int jp = 0; jp < 4; jp++) {
                const int mrow = 8 * (2 * jp + ((lane >> 4) & 1)) + (lane & 7);
                const int mcol = 16 * c + ((lane >> 3) & 1) * 8;
                const uint32_t ad = u + mrow * KSTR + mcol * 2;
                uint32_t bh[4], bl[4];
                ldm_x4(bh, ad);
                ldm_x4(bl, ad + KARR);
                mma_f32acc(Sf[2 * jp],     qh[c], &bh[0]);
                mma_f16acc(Sc[2 * jp],     qh[c], &bl[0]);
                mma_f16acc(Sc[2 * jp],     ql[c], &bh[0]);
                mma_f32acc(Sf[2 * jp + 1], qh[c], &bh[2]);
                mma_f16acc(Sc[2 * jp + 1], qh[c], &bl[2]);
                mma_f16acc(Sc[2 * jp + 1], ql[c], &bh[2]);
            }
        }
        #pragma unroll
        for (int j = 0; j < 8; j++) merge_corr(Sf[j], Sc[j]);

        // ---- bias + mask ----
        const float* bt = bb + (size_t)kt * 64;
        #pragma unroll
        for (int j = 0; j < 8; j++) {
            float2 mv = *reinterpret_cast<const float2*>(sma + (kt & 1) * STG_ATT + MOFF
                                                         + (8 * j + 2 * tg) * 4);
            float2 bv0 = *reinterpret_cast<const float2*>(bt + (size_t)g * Nn + 8 * j + 2 * tg);
            float2 bv1 = *reinterpret_cast<const float2*>(bt + (size_t)(g + 8) * Nn + 8 * j + 2 * tg);
            Sf[j][0] += bv0.x + mv.x; Sf[j][1] += bv0.y + mv.y;
            Sf[j][2] += bv1.x + mv.x; Sf[j][3] += bv1.y + mv.y;
        }

        // ---- online softmax on fragments ----
        float mx0 = -3e38f, mx1 = -3e38f;
        #pragma unroll
        for (int j = 0; j < 8; j++) {
            mx0 = fmaxf(mx0, fmaxf(Sf[j][0], Sf[j][1]));
            mx1 = fmaxf(mx1, fmaxf(Sf[j][2], Sf[j][3]));
        }
        #pragma unroll
        for (int off = 1; off < 4; off <<= 1) {
            mx0 = fmaxf(mx0, __shfl_xor_sync(0xffffffffu, mx0, off));
            mx1 = fmaxf(mx1, __shfl_xor_sync(0xffffffffu, mx1, off));
        }
        const float mn0 = fmaxf(m0r, mx0), mn1 = fmaxf(m1r, mx1);
        const float sc0 = __expf(m0r - mn0), sc1 = __expf(m1r - mn1);
        m0r = mn0; m1r = mn1;
        float sum0 = 0.0f, sum1 = 0.0f;
        #pragma unroll
        for (int j = 0; j < 8; j++) {
            Sf[j][0] = __expf(Sf[j][0] - mn0);
            Sf[j][1] = __expf(Sf[j][1] - mn0);
            Sf[j][2] = __expf(Sf[j][2] - mn1);
            Sf[j][3] = __expf(Sf[j][3] - mn1);
            sum0 += Sf[j][0] + Sf[j][1];
            sum1 += Sf[j][2] + Sf[j][3];
        }
        #pragma unroll
        for (int off = 1; off < 4; off <<= 1) {
            sum0 += __shfl_xor_sync(0xffffffffu, sum0, off);
            sum1 += __shfl_xor_sync(0xffffffffu, sum1, off);
        }
        l0 = l0 * sc0 + sum0;
        l1 = l1 * sc1 + sum1;
        #pragma unroll
        for (int j = 0; j < 8; j++) {
            O[j][0] *= sc0; O[j][1] *= sc0;
            O[j][2] *= sc1; O[j][3] *= sc1;
        }

        // ---- O += P V (fp16x3: hh f32-acc, corrections f16-acc per tile) ----
        const uint32_t uV = u + VOFF;
        uint32_t Oc[8][2];
        #pragma unroll
        for (int j = 0; j < 8; j++) { Oc[j][0] = 0u; Oc[j][1] = 0u; }
        #pragma unroll
        for (int c = 0; c < 4; c++) {
            uint32_t ph[4], pl[4];
            packhl(Sf[2 * c][0],     Sf[2 * c][1],     ph[0], pl[0]);
            packhl(Sf[2 * c][2],     Sf[2 * c][3],     ph[1], pl[1]);
            packhl(Sf[2 * c + 1][0], Sf[2 * c + 1][1], ph[2], pl[2]);
            packhl(Sf[2 * c + 1][2], Sf[2 * c + 1][3], ph[3], pl[3]);
            #pragma unroll
            for (int jp = 0; jp < 4; jp++) {
                const int mrow = 8 * (2 * jp + ((lane >> 4) & 1)) + (lane & 7);
                const int mcol = 16 * c + ((lane >> 3) & 1) * 8;
                const uint32_t ad = uV + mrow * VSTR + mcol * 2;
                uint32_t vh[4], vl[4];
                ldm_x4(vh, ad);
                ldm_x4(vl, ad + VARR);
                mma_f32acc(O[2 * jp],      ph, &vh[0]);
                mma_f16acc(Oc[2 * jp],     ph, &vl[0]);
                mma_f16acc(Oc[2 * jp],     pl, &vh[0]);
                mma_f32acc(O[2 * jp + 1],  ph, &vh[2]);
                mma_f16acc(Oc[2 * jp + 1], ph, &vl[2]);
                mma_f16acc(Oc[2 * jp + 1], pl, &vh[2]);
            }
        }
        #pragma unroll
        for (int j = 0; j < 8; j++) merge_corr(O[j], Oc[j]);
    }

    // ---- normalize + write split fp16 ----
    const float inv0 = 1.0f / l0, inv1 = 1.0f / l1;
    const size_t rbase = (size_t)(b * Nn + q0 + w * 16) * Dn + h * HDn;
    #pragma unroll
    for (int j = 0; j < 8; j++) {
        const int col = 8 * j + 2 * tg;
        uint32_t hv, lv;
        packhl(O[j][0] * inv0, O[j][1] * inv0, hv, lv);
        *reinterpret_cast<uint32_t*>(&g_oh[rbase + (size_t)g * Dn + col]) = hv;
        *reinterpret_cast<uint32_t*>(&g_ol[rbase + (size_t)g * Dn + col]) = lv;
        packhl(O[j][2] * inv1, O[j][3] * inv1, hv, lv);
        *reinterpret_cast<uint32_t*>(&g_oh[rbase + (size_t)(g + 8) * Dn + col]) = hv;
        *reinterpret_cast<uint32_t*>(&g_ol[rbase + (size_t)(g + 8) * Dn + col]) = lv;
    }
}

// ---------------------------------------------------------------------------
// Launch. Inputs (metadata order): q, mask, attn_bias, Wq, Wk, Wv, Wo
// ---------------------------------------------------------------------------
extern "C" void kernel_launch(void* const* d_in, const int* in_sizes, int n_in,
                              void* d_out, int out_size) {
    const float* q    = (const float*)d_in[0];
    const int*   mask = (const int*)d_in[1];
    const float* bias = (const float*)d_in[2];
    const float* Wq   = (const float*)d_in[3];
    const float* Wk   = (const float*)d_in[4];
    const float* Wv   = (const float*)d_in[5];
    const float* Wo   = (const float*)d_in[6];
    float* out = (float*)d_out;

    cudaFuncSetAttribute(gemm_qkv, cudaFuncAttributeMaxDynamicSharedMemorySize, SMEM_GEMM);
    cudaFuncSetAttribute(gemm_out, cudaFuncAttributeMaxDynamicSharedMemorySize, SMEM_GEMM);
    cudaFuncSetAttribute(attn_mma, cudaFuncAttributeMaxDynamicSharedMemorySize, SMEM_ATT);

    mask_prep<<<32, 256>>>(mask);
    prep_split_x<<<MT * Dn / 4 / 256, 256>>>((const float4*)q);
    prep_split_w<<<dim3(Dn * Dn / 4 / 256, 4), 256>>>(
        (const float4*)Wq, (const float4*)Wk, (const float4*)Wv, (const float4*)Wo);

    gemm_qkv<<<dim3(Dn / 128, MT / 256, 3), 256, SMEM_GEMM>>>();

    attn_mma<<<dim3(Hn, Nn / 128, Bn), 256, SMEM_ATT>>>(bias);

    gemm_out<<<dim3(Dn / 128, MT / 256, 1), 256, SMEM_GEMM>>>(out);
}

// round 13
// speedup vs baseline: 2.3306x; 2.3306x over previous
#include <cuda_runtime.h>
#include <cuda_fp16.h>
#include <cstdint>

// Problem constants
#define Bn  4
#define Nn  2048
#define Dn  512
#define Hn  8
#define HDn 64
#define MT  (Bn*Nn)   // 8192 rows

// Scratch (allocation-free rule: __device__ globals) — fp16 splits
// A-side operands keep hi+lo; B-side operands are single fp16 (error 2^-12).
__device__ __half g_xh[MT*Dn], g_xl[MT*Dn];           // input q split (A-side)
__device__ __half g_wh[4*Dn*Dn];                      // Wq,Wk,Wv,Wo hi only (B-side)
__device__ __half g_qh[MT*Dn], g_ql[MT*Dn];           // Q proj split (A-side of S), scaled 1/8
__device__ __half g_kh[MT*Dn];                        // K proj hi only (B-side of S)
__device__ __half g_vth[MT*Dn];                       // V proj transposed hi only (B-side of PV)
__device__ __half g_oh[MT*Dn], g_ol[MT*Dn];           // attention output split (A-side of out proj)
__device__ float g_maskf[Bn*Nn];

// ===========================================================================
// common helpers
// ===========================================================================
__device__ __forceinline__ uint32_t smem_u32(const void* p) {
    uint32_t a;
    asm("{ .reg .u64 t; cvta.to.shared.u64 t, %1; cvt.u32.u64 %0, t; }" : "=r"(a) : "l"(p));
    return a;
}
__device__ __forceinline__ void mma_f16(float* c, const uint32_t* a, const uint32_t* b) {
    asm volatile("mma.sync.aligned.m16n8k16.row.col.f32.f16.f16.f32 "
        "{%0,%1,%2,%3}, {%4,%5,%6,%7}, {%8,%9}, {%0,%1,%2,%3};"
        : "+f"(c[0]), "+f"(c[1]), "+f"(c[2]), "+f"(c[3])
        : "r"(a[0]), "r"(a[1]), "r"(a[2]), "r"(a[3]), "r"(b[0]), "r"(b[1]));
}
__device__ __forceinline__ void ldm_x4(uint32_t* r, uint32_t saddr) {
    asm volatile("ldmatrix.sync.aligned.m8n8.x4.shared.b16 {%0,%1,%2,%3}, [%4];"
        : "=r"(r[0]), "=r"(r[1]), "=r"(r[2]), "=r"(r[3]) : "r"(saddr));
}
__device__ __forceinline__ void cp16(uint32_t saddr, const void* g) {
    asm volatile("cp.async.ca.shared.global [%0], [%1], 16;" :: "r"(saddr), "l"(g));
}
__device__ __forceinline__ void cp_commit() { asm volatile("cp.async.commit_group;" ::: "memory"); }
__device__ __forceinline__ void cp_wait0()  { asm volatile("cp.async.wait_group 0;" ::: "memory"); }
__device__ __forceinline__ void cp_wait1()  { asm volatile("cp.async.wait_group 1;" ::: "memory"); }

__device__ __forceinline__ uint32_t packh_hi(float x, float y, float& rx, float& ry) {
    __half hx = __float2half_rn(x), hy = __float2half_rn(y);
    rx = x - __half2float(hx);
    ry = y - __half2float(hy);
    return (uint32_t)__half_as_ushort(hx) | ((uint32_t)__half_as_ushort(hy) << 16);
}
__device__ __forceinline__ uint32_t packh(float x, float y) {
    return (uint32_t)__half_as_ushort(__float2half_rn(x)) |
           ((uint32_t)__half_as_ushort(__float2half_rn(y)) << 16);
}
__device__ __forceinline__ void packhl(float x, float y, uint32_t& h, uint32_t& l) {
    float rx, ry;
    h = packh_hi(x, y, rx, ry);
    l = packh(rx, ry);
}

// ===========================================================================
// prep: mask -> float addend; fp32 -> fp16 splits
// ===========================================================================
__global__ void mask_prep(const int* __restrict__ mask) {
    int i = blockIdx.x * blockDim.x + threadIdx.x;
    if (i < Bn * Nn) g_maskf[i] = mask[i] ? -1e30f : 0.0f;
}

__global__ void prep_split_x(const float4* __restrict__ src) {
    int i = blockIdx.x * blockDim.x + threadIdx.x;      // over MT*Dn/4
    float4 v = src[i];
    float r0, r1, r2, r3;
    uint32_t h0 = packh_hi(v.x, v.y, r0, r1);
    uint32_t h1 = packh_hi(v.z, v.w, r2, r3);
    reinterpret_cast<uint2*>(g_xh)[i] = make_uint2(h0, h1);
    reinterpret_cast<uint2*>(g_xl)[i] = make_uint2(packh(r0, r1), packh(r2, r3));
}

__global__ void prep_round_w(const float4* __restrict__ w0, const float4* __restrict__ w1,
                             const float4* __restrict__ w2, const float4* __restrict__ w3) {
    int i = blockIdx.x * blockDim.x + threadIdx.x;      // over Dn*Dn/4
    int z = blockIdx.y;
    const float4* src = (z == 0) ? w0 : (z == 1) ? w1 : (z == 2) ? w2 : w3;
    float4 v = src[i];
    reinterpret_cast<uint2*>(g_wh)[(size_t)z * (Dn * Dn / 4) + i] =
        make_uint2(packh(v.x, v.y), packh(v.z, v.w));
}

// ===========================================================================
// fp16x2 GEMM: CTA tile 256x128, 8 warps as 4(m) x 2(n), warp tile 64x64.
// BK=32, 2-stage cp.async, ldmatrix. A = hi+lo, B = hi only.
// Per product: ah*bh + al*bh (f32 accum).
// ===========================================================================
#define BK    32
#define SAstr 40                    // fp16 elems per smem row (80 B)
#define GA_AH 0
#define GA_AL 20480                 // 256*80
#define GA_BH 40960                 // +256*80
#define GSTG  51200                 // + 128*80
#define SMEM_GEMM (2*GSTG)          // 102400 B
#define NCH   (Dn/BK)               // 16

#define GEMM_MAINLOOP(AH, AL, BH, ACC) \
    const uint32_t sU = smem_u32(smg); \
    const __half* Ah_g = (AH) + (size_t)m0 * Dn; \
    const __half* Al_g = (AL) + (size_t)m0 * Dn; \
    const __half* Bh_g = (BH) + (size_t)n0 * Dn; \
    auto prefetch = [&](int kc) { \
        const uint32_t u = sU + (kc & 1) * GSTG; \
        _Pragma("unroll") \
        for (int t = 0; t < 4; t++) {                /* A: 256 rows x 4 chunks */ \
            int id = tid + t * 256; \
            int row = id >> 2, c = id & 3; \
            size_t go = (size_t)row * Dn + kc * BK + c * 8; \
            uint32_t so = u + row * (SAstr * 2) + c * 16; \
            cp16(so + GA_AH, Ah_g + go); \
            cp16(so + GA_AL, Al_g + go); \
        } \
        _Pragma("unroll") \
        for (int t = 0; t < 2; t++) {                /* B: 128 rows x 4 chunks */ \
            int id = tid + t * 256; \
            int row = id >> 2, c = id & 3; \
            size_t go = (size_t)row * Dn + kc * BK + c * 8; \
            uint32_t so = u + row * (SAstr * 2) + c * 16; \
            cp16(so + GA_BH, Bh_g + go); \
        } \
        cp_commit(); \
    }; \
    prefetch(0); \
    _Pragma("unroll 1") \
    for (int kc = 0; kc < NCH; kc++) { \
        if (kc + 1 < NCH) { prefetch(kc + 1); cp_wait1(); } else { cp_wait0(); } \
        __syncthreads(); \
        const uint32_t s = sU + (kc & 1) * GSTG; \
        _Pragma("unroll") \
        for (int ks = 0; ks < 2; ks++) { \
            const int k0 = ks * 16; \
            uint32_t ah[4][4], al[4][4]; \
            _Pragma("unroll") \
            for (int t = 0; t < 4; t++) { \
                uint32_t ra = wm + t * 16 + (lane & 15); \
                uint32_t ad = s + (ra * SAstr + k0 + (lane >> 4) * 8) * 2; \
                ldm_x4(ah[t], ad + GA_AH); \
                ldm_x4(al[t], ad + GA_AL); \
            } \
            _Pragma("unroll") \
            for (int jj = 0; jj < 4; jj++) { \
                uint32_t rb = wn + 8 * (2 * jj + ((lane >> 4) & 1)) + (lane & 7); \
                uint32_t ad = s + (rb * SAstr + k0 + ((lane >> 3) & 1) * 8) * 2; \
                uint32_t bh[4]; \
                ldm_x4(bh, ad + GA_BH); \
                _Pragma("unroll") \
                for (int t = 0; t < 4; t++) { \
                    mma_f16(ACC[t][2 * jj],     ah[t], &bh[0]); \
                    mma_f16(ACC[t][2 * jj],     al[t], &bh[0]); \
                    mma_f16(ACC[t][2 * jj + 1], ah[t], &bh[2]); \
                    mma_f16(ACC[t][2 * jj + 1], al[t], &bh[2]); \
                } \
            } \
        } \
        __syncthreads(); \
    }

// ---------------------------------------------------------------------------
// QKV projection GEMM: z=0 Q (scaled 1/8, split), z=1 K (hi only),
// z=2 V (smem-transposed, hi only)
// ---------------------------------------------------------------------------
#define TSTR2 264    // V-transpose smem: tokens per d-row (528 B, 16B-mult)

__global__ __launch_bounds__(256, 1) void gemm_qkv() {
    extern __shared__ __align__(16) char smg[];
    const int tid  = threadIdx.x;
    const int lane = tid & 31;
    const int g    = lane >> 2;
    const int tg   = lane & 3;
    const int wid  = tid >> 5;
    const int n0 = blockIdx.x * 128, m0 = blockIdx.y * 256;
    const int z  = blockIdx.z;
    const int wm = (wid & 3) * 64;     // 4 warps along M (256)
    const int wn = (wid >> 2) * 64;    // 2 warps along N (128)

    float acc[4][8][4];
    #pragma unroll
    for (int t = 0; t < 4; t++)
        #pragma unroll
        for (int j = 0; j < 8; j++)
            #pragma unroll
            for (int e = 0; e < 4; e++) acc[t][j][e] = 0.0f;

    const __half* Wh = g_wh + (size_t)z * Dn * Dn;
    GEMM_MAINLOOP(g_xh, g_xl, Wh, acc)

    if (z == 0) {
        // Q: scale 1/8, split hi/lo (A-side of S)
        #pragma unroll
        for (int t = 0; t < 4; t++)
            #pragma unroll
            for (int j = 0; j < 8; j++) {
                int r = m0 + wm + t * 16 + g;
                int c = n0 + wn + j * 8 + tg * 2;
                float v0 = acc[t][j][0] * 0.125f, v1 = acc[t][j][1] * 0.125f;
                float v2 = acc[t][j][2] * 0.125f, v3 = acc[t][j][3] * 0.125f;
                uint32_t h, l;
                packhl(v0, v1, h, l);
                *reinterpret_cast<uint32_t*>(&g_qh[(size_t)r * Dn + c]) = h;
                *reinterpret_cast<uint32_t*>(&g_ql[(size_t)r * Dn + c]) = l;
                packhl(v2, v3, h, l);
                *reinterpret_cast<uint32_t*>(&g_qh[(size_t)(r + 8) * Dn + c]) = h;
                *reinterpret_cast<uint32_t*>(&g_ql[(size_t)(r + 8) * Dn + c]) = l;
            }
    } else if (z == 1) {
        // K: hi only (B-side of S)
        #pragma unroll
        for (int t = 0; t < 4; t++)
            #pragma unroll
            for (int j = 0; j < 8; j++) {
                int r = m0 + wm + t * 16 + g;
                int c = n0 + wn + j * 8 + tg * 2;
                *reinterpret_cast<uint32_t*>(&g_kh[(size_t)r * Dn + c]) =
                    packh(acc[t][j][0], acc[t][j][1]);
                *reinterpret_cast<uint32_t*>(&g_kh[(size_t)(r + 8) * Dn + c]) =
                    packh(acc[t][j][2], acc[t][j][3]);
            }
    } else {
        // V: transpose through smem (hi only), coalesced out
        #pragma unroll
        for (int t = 0; t < 4; t++)
            #pragma unroll
            for (int j = 0; j < 8; j++)
                #pragma unroll
                for (int e = 0; e < 4; e++) {
                    int lr = wm + t * 16 + g + (e >> 1) * 8;   // local token 0..255
                    int lc = wn + j * 8 + tg * 2 + (e & 1);    // local dim 0..127
                    *reinterpret_cast<__half*>(smg + (size_t)lc * (TSTR2 * 2) + lr * 2) =
                        __float2half_rn(acc[t][j][e]);
                }
        __syncthreads();
        const int dd = tid >> 1;          // 0..127 (local dim)
        const int hf = tid & 1;           // token half (128 each)
        const int b  = m0 >> 11;
        const int hh = (n0 + dd) >> 6;
        const int d  = (n0 + dd) & 63;
        const size_t dst = (((size_t)(b * Hn + hh)) * HDn + d) * Nn + (m0 & (Nn - 1)) + hf * 128;
        const uint32_t so = (uint32_t)dd * (TSTR2 * 2) + hf * 256;
        #pragma unroll
        for (int u = 0; u < 16; u++)
            *reinterpret_cast<uint4*>(&g_vth[dst + u * 8]) =
                *reinterpret_cast<const uint4*>(smg + so + u * 16);
    }
}

// ---------------------------------------------------------------------------
// Output projection GEMM: reads split O (A-side), Wo hi (B-side), writes fp32
// ---------------------------------------------------------------------------
__global__ __launch_bounds__(256, 1) void gemm_out(float* __restrict__ C) {
    extern __shared__ __align__(16) char smg[];
    const int tid  = threadIdx.x;
    const int lane = tid & 31;
    const int g    = lane >> 2;
    const int tg   = lane & 3;
    const int wid  = tid >> 5;
    const int n0 = blockIdx.x * 128, m0 = blockIdx.y * 256;
    const int wm = (wid & 3) * 64;
    const int wn = (wid >> 2) * 64;

    float acc[4][8][4];
    #pragma unroll
    for (int t = 0; t < 4; t++)
        #pragma unroll
        for (int j = 0; j < 8; j++)
            #pragma unroll
            for (int e = 0; e < 4; e++) acc[t][j][e] = 0.0f;

    const __half* Wh = g_wh + (size_t)3 * Dn * Dn;
    GEMM_MAINLOOP(g_oh, g_ol, Wh, acc)

    #pragma unroll
    for (int t = 0; t < 4; t++)
        #pragma unroll
        for (int j = 0; j < 8; j++) {
            int row = m0 + wm + t * 16 + g;
            int col = n0 + wn + j * 8 + tg * 2;
            *reinterpret_cast<float2*>(C + (size_t)row * Dn + col) =
                make_float2(acc[t][j][0], acc[t][j][1]);
            *reinterpret_cast<float2*>(C + (size_t)(row + 8) * Dn + col) =
                make_float2(acc[t][j][2], acc[t][j][3]);
        }
}

// ===========================================================================
// Tensor-core flash attention: 128 q-rows per CTA (8 warps x 16 rows),
// k-tiles of 64 keys, fp16x2 (Q/P split, K/V hi only), cp.async double
// buffer, 2 CTAs/SM.
// ===========================================================================
#define KSTR 144
#define VSTR 144
#define KARR (64*KSTR)                // 9216 (K hi)
#define VOFF KARR                     // V hi at +9216
#define MOFF (2*KARR)                 // mask at +18432
#define STG_ATT (MOFF + 256)          // 18688
#define SMEM_ATT (2*STG_ATT)          // 37376

__global__ __launch_bounds__(256, 2) void attn_mma(const float* __restrict__ bias) {
    extern __shared__ __align__(16) char sma[];
    const uint32_t sb = smem_u32(sma);
    const int tid  = threadIdx.x;
    const int lane = tid & 31;
    const int w    = tid >> 5;
    const int g    = lane >> 2;
    const int tg   = lane & 3;
    const int h  = blockIdx.x;
    const int q0 = blockIdx.y * 128;
    const int b  = blockIdx.z;

    // ---- Q fragments from gmem (once) ----
    uint32_t qh[4][4], ql[4][4];
    {
        const size_t rbase = (size_t)(b * Nn + q0 + w * 16) * Dn + h * HDn;
        #pragma unroll
        for (int c = 0; c < 4; c++) {
            size_t o0 = rbase + (size_t)g * Dn + c * 16 + tg * 2;
            size_t o1 = rbase + (size_t)(g + 8) * Dn + c * 16 + tg * 2;
            qh[c][0] = *reinterpret_cast<const uint32_t*>(&g_qh[o0]);
            qh[c][1] = *reinterpret_cast<const uint32_t*>(&g_qh[o1]);
            qh[c][2] = *reinterpret_cast<const uint32_t*>(&g_qh[o0 + 8]);
            qh[c][3] = *reinterpret_cast<const uint32_t*>(&g_qh[o1 + 8]);
            ql[c][0] = *reinterpret_cast<const uint32_t*>(&g_ql[o0]);
            ql[c][1] = *reinterpret_cast<const uint32_t*>(&g_ql[o1]);
            ql[c][2] = *reinterpret_cast<const uint32_t*>(&g_ql[o0 + 8]);
            ql[c][3] = *reinterpret_cast<const uint32_t*>(&g_ql[o1 + 8]);
        }
    }

    const char* kh_base = (const char*)g_kh + ((size_t)(b * Nn) * Dn + h * HDn) * 2;
    const char* vh_base = (const char*)g_vth + ((size_t)(b * Hn + h) * HDn) * Nn * 2;
    const char* mk_base = (const char*)g_maskf + (size_t)(b * Nn) * 4;

    auto prefetch = [&](int kt) {
        const uint32_t u = sb + (kt & 1) * STG_ATT;
        const size_t kof = (size_t)kt * 64 * (Dn * 2);
        #pragma unroll
        for (int t = 0; t < 2; t++) {
            int id = tid + t * 256;           // 512 = 64 rows x 8 chunks
            int row = id >> 3, c = id & 7;
            cp16(u + row * KSTR + c * 16,        kh_base + kof + (size_t)row * (Dn * 2) + c * 16);
            cp16(u + VOFF + row * VSTR + c * 16,
                 vh_base + (size_t)row * (Nn * 2) + kt * 128 + c * 16);
        }
        if (tid < 16) cp16(u + MOFF + tid * 16, mk_base + (size_t)kt * 256 + tid * 16);
        cp_commit();
    };

    float O[8][4];
    #pragma unroll
    for (int j = 0; j < 8; j++)
        #pragma unroll
        for (int e = 0; e < 4; e++) O[j][e] = 0.0f;
    float m0r = -3e38f, m1r = -3e38f, l0 = 0.0f, l1 = 0.0f;

    prefetch(0);

    const float* bb = bias + ((size_t)(b * Nn) + q0 + w * 16) * Nn;

    #pragma unroll 1
    for (int kt = 0; kt < Nn / 64; kt++) {
        cp_wait0();
        __syncthreads();
        const uint32_t u = sb + (kt & 1) * STG_ATT;
        if (kt + 1 < Nn / 64) prefetch(kt + 1);

        // ---- S = Q K^T (fp16x2: qh+ql vs kh) ----
        float Sf[8][4];
        #pragma unroll
        for (int j = 0; j < 8; j++)
            #pragma unroll
            for (int e = 0; e < 4; e++) Sf[j][e] = 0.0f;

        #pragma unroll
        for (int c = 0; c < 4; c++) {
            #pragma unroll
            for (int jp = 0; jp < 4; jp++) {
                const int mrow = 8 * (2 * jp + ((lane >> 4) & 1)) + (lane & 7);
                const int mcol = 16 * c + ((lane >> 3) & 1) * 8;
                const uint32_t ad = u + mrow * KSTR + mcol * 2;
                uint32_t bh[4];
                ldm_x4(bh, ad);
                mma_f16(Sf[2 * jp],     qh[c], &bh[0]);
                mma_f16(Sf[2 * jp],     ql[c], &bh[0]);
                mma_f16(Sf[2 * jp + 1], qh[c], &bh[2]);
                mma_f16(Sf[2 * jp + 1], ql[c], &bh[2]);
            }
        }

        // ---- bias + mask ----
        const float* bt = bb + (size_t)kt * 64;
        #pragma unroll
        for (int j = 0; j < 8; j++) {
            float2 mv = *reinterpret_cast<const float2*>(sma + (kt & 1) * STG_ATT + MOFF
                                                         + (8 * j + 2 * tg) * 4);
            float2 bv0 = *reinterpret_cast<const float2*>(bt + (size_t)g * Nn + 8 * j + 2 * tg);
            float2 bv1 = *reinterpret_cast<const float2*>(bt + (size_t)(g + 8) * Nn + 8 * j + 2 * tg);
            Sf[j][0] += bv0.x + mv.x; Sf[j][1] += bv0.y + mv.y;
            Sf[j][2] += bv1.x + mv.x; Sf[j][3] += bv1.y + mv.y;
        }

        // ---- online softmax on fragments ----
        float mx0 = -3e38f, mx1 = -3e38f;
        #pragma unroll
        for (int j = 0; j < 8; j++) {
            mx0 = fmaxf(mx0, fmaxf(Sf[j][0], Sf[j][1]));
            mx1 = fmaxf(mx1, fmaxf(Sf[j][2], Sf[j][3]));
        }
        #pragma unroll
        for (int off = 1; off < 4; off <<= 1) {
            mx0 = fmaxf(mx0, __shfl_xor_sync(0xffffffffu, mx0, off));
            mx1 = fmaxf(mx1, __shfl_xor_sync(0xffffffffu, mx1, off));
        }
        const float mn0 = fmaxf(m0r, mx0), mn1 = fmaxf(m1r, mx1);
        const float sc0 = __expf(m0r - mn0), sc1 = __expf(m1r - mn1);
        m0r = mn0; m1r = mn1;
        float sum0 = 0.0f, sum1 = 0.0f;
        #pragma unroll
        for (int j = 0; j < 8; j++) {
            Sf[j][0] = __expf(Sf[j][0] - mn0);
            Sf[j][1] = __expf(Sf[j][1] - mn0);
            Sf[j][2] = __expf(Sf[j][2] - mn1);
            Sf[j][3] = __expf(Sf[j][3] - mn1);
            sum0 += Sf[j][0] + Sf[j][1];
            sum1 += Sf[j][2] + Sf[j][3];
        }
        #pragma unroll
        for (int off = 1; off < 4; off <<= 1) {
            sum0 += __shfl_xor_sync(0xffffffffu, sum0, off);
            sum1 += __shfl_xor_sync(0xffffffffu, sum1, off);
        }
        l0 = l0 * sc0 + sum0;
        l1 = l1 * sc1 + sum1;
        #pragma unroll
        for (int j = 0; j < 8; j++) {
            O[j][0] *= sc0; O[j][1] *= sc0;
            O[j][2] *= sc1; O[j][3] *= sc1;
        }

        // ---- O += P V (fp16x2: ph+pl vs vh) ----
        const uint32_t uV = u + VOFF;
        #pragma unroll
        for (int c = 0; c < 4; c++) {
            uint32_t ph[4], pl[4];
            packhl(Sf[2 * c][0],     Sf[2 * c][1],     ph[0], pl[0]);
            packhl(Sf[2 * c][2],     Sf[2 * c][3],     ph[1], pl[1]);
            packhl(Sf[2 * c + 1][0], Sf[2 * c + 1][1], ph[2], pl[2]);
            packhl(Sf[2 * c + 1][2], Sf[2 * c + 1][3], ph[3], pl[3]);
            #pragma unroll
            for (int jp = 0; jp < 4; jp++) {
                const int mrow = 8 * (2 * jp + ((lane >> 4) & 1)) + (lane & 7);
                const int mcol = 16 * c + ((lane >> 3) & 1) * 8;
                const uint32_t ad = uV + mrow * VSTR + mcol * 2;
                uint32_t vh[4];
                ldm_x4(vh, ad);
                mma_f16(O[2 * jp],     ph, &vh[0]);
                mma_f16(O[2 * jp],     pl, &vh[0]);
                mma_f16(O[2 * jp + 1], ph, &vh[2]);
                mma_f16(O[2 * jp + 1], pl, &vh[2]);
            }
        }
    }

    // ---- normalize + write split fp16 (A-side of out proj) ----
    const float inv0 = 1.0f / l0, inv1 = 1.0f / l1;
    const size_t rbase = (size_t)(b * Nn + q0 + w * 16) * Dn + h * HDn;
    #pragma unroll
    for (int j = 0; j < 8; j++) {
        const int col = 8 * j + 2 * tg;
        uint32_t hv, lv;
        packhl(O[j][0] * inv0, O[j][1] * inv0, hv, lv);
        *reinterpret_cast<uint32_t*>(&g_oh[rbase + (size_t)g * Dn + col]) = hv;
        *reinterpret_cast<uint32_t*>(&g_ol[rbase + (size_t)g * Dn + col]) = lv;
        packhl(O[j][2] * inv1, O[j][3] * inv1, hv, lv);
        *reinterpret_cast<uint32_t*>(&g_oh[rbase + (size_t)(g + 8) * Dn + col]) = hv;
        *reinterpret_cast<uint32_t*>(&g_ol[rbase + (size_t)(g + 8) * Dn + col]) = lv;
    }
}

// ---------------------------------------------------------------------------
// Launch. Inputs (metadata order): q, mask, attn_bias, Wq, Wk, Wv, Wo
// ---------------------------------------------------------------------------
extern "C" void kernel_launch(void* const* d_in, const int* in_sizes, int n_in,
                              void* d_out, int out_size) {
    const float* q    = (const float*)d_in[0];
    const int*   mask = (const int*)d_in[1];
    const float* bias = (const float*)d_in[2];
    const float* Wq   = (const float*)d_in[3];
    const float* Wk   = (const float*)d_in[4];
    const float* Wv   = (const float*)d_in[5];
    const float* Wo   = (const float*)d_in[6];
    float* out = (float*)d_out;

    cudaFuncSetAttribute(gemm_qkv, cudaFuncAttributeMaxDynamicSharedMemorySize, SMEM_GEMM);
    cudaFuncSetAttribute(gemm_out, cudaFuncAttributeMaxDynamicSharedMemorySize, SMEM_GEMM);
    cudaFuncSetAttribute(attn_mma, cudaFuncAttributeMaxDynamicSharedMemorySize, SMEM_ATT);

    mask_prep<<<32, 256>>>(mask);
    prep_split_x<<<MT * Dn / 4 / 256, 256>>>((const float4*)q);
    prep_round_w<<<dim3(Dn * Dn / 4 / 256, 4), 256>>>(
        (const float4*)Wq, (const float4*)Wk, (const float4*)Wv, (const float4*)Wo);

    gemm_qkv<<<dim3(Dn / 128, MT / 256, 3), 256, SMEM_GEMM>>>();

    attn_mma<<<dim3(Hn, Nn / 128, Bn), 256, SMEM_ATT>>>(bias);

    gemm_out<<<dim3(Dn / 128, MT / 256, 1), 256, SMEM_GEMM>>>(out);
}

// round 14
// speedup vs baseline: 2.6380x; 1.1319x over previous
#include <cuda_runtime.h>
#include <cuda_fp16.h>
#include <cstdint>

// Problem constants
#define Bn  4
#define Nn  2048
#define Dn  512
#define Hn  8
#define HDn 64
#define MT  (Bn*Nn)   // 8192 rows

// Scratch (allocation-free rule: __device__ globals) — fp16 splits
// A-side of projections keeps hi+lo; everything else single fp16 where the
// rounding error is incoherent (averages out over the contraction).
__device__ __half g_xh[MT*Dn], g_xl[MT*Dn];           // input q split (A-side)
__device__ __half g_wh[4*Dn*Dn];                      // Wq,Wk,Wv,Wo hi only (B-side)
__device__ __half g_qh[MT*Dn], g_ql[MT*Dn];           // Q proj split (A-side of S), scaled 1/8
__device__ __half g_kh[MT*Dn];                        // K proj hi only (B-side of S)
__device__ __half g_vth[MT*Dn];                       // V proj transposed hi only (B-side of PV)
__device__ __half g_oh[MT*Dn];                        // attention output hi only (A-side of out proj)
__device__ float g_maskf[Bn*Nn];

// ===========================================================================
// common helpers
// ===========================================================================
__device__ __forceinline__ uint32_t smem_u32(const void* p) {
    uint32_t a;
    asm("{ .reg .u64 t; cvta.to.shared.u64 t, %1; cvt.u32.u64 %0, t; }" : "=r"(a) : "l"(p));
    return a;
}
__device__ __forceinline__ void mma_f16(float* c, const uint32_t* a, const uint32_t* b) {
    asm volatile("mma.sync.aligned.m16n8k16.row.col.f32.f16.f16.f32 "
        "{%0,%1,%2,%3}, {%4,%5,%6,%7}, {%8,%9}, {%0,%1,%2,%3};"
        : "+f"(c[0]), "+f"(c[1]), "+f"(c[2]), "+f"(c[3])
        : "r"(a[0]), "r"(a[1]), "r"(a[2]), "r"(a[3]), "r"(b[0]), "r"(b[1]));
}
__device__ __forceinline__ void ldm_x4(uint32_t* r, uint32_t saddr) {
    asm volatile("ldmatrix.sync.aligned.m8n8.x4.shared.b16 {%0,%1,%2,%3}, [%4];"
        : "=r"(r[0]), "=r"(r[1]), "=r"(r[2]), "=r"(r[3]) : "r"(saddr));
}
__device__ __forceinline__ void cp16(uint32_t saddr, const void* g) {
    asm volatile("cp.async.ca.shared.global [%0], [%1], 16;" :: "r"(saddr), "l"(g));
}
__device__ __forceinline__ void cp_commit() { asm volatile("cp.async.commit_group;" ::: "memory"); }
__device__ __forceinline__ void cp_wait0()  { asm volatile("cp.async.wait_group 0;" ::: "memory"); }
__device__ __forceinline__ void cp_wait1()  { asm volatile("cp.async.wait_group 1;" ::: "memory"); }

__device__ __forceinline__ uint32_t packh_hi(float x, float y, float& rx, float& ry) {
    __half hx = __float2half_rn(x), hy = __float2half_rn(y);
    rx = x - __half2float(hx);
    ry = y - __half2float(hy);
    return (uint32_t)__half_as_ushort(hx) | ((uint32_t)__half_as_ushort(hy) << 16);
}
__device__ __forceinline__ uint32_t packh(float x, float y) {
    return (uint32_t)__half_as_ushort(__float2half_rn(x)) |
           ((uint32_t)__half_as_ushort(__float2half_rn(y)) << 16);
}
__device__ __forceinline__ void packhl(float x, float y, uint32_t& h, uint32_t& l) {
    float rx, ry;
    h = packh_hi(x, y, rx, ry);
    l = packh(rx, ry);
}

// ===========================================================================
// prep: mask -> float addend; fp32 -> fp16 splits
// ===========================================================================
__global__ void mask_prep(const int* __restrict__ mask) {
    int i = blockIdx.x * blockDim.x + threadIdx.x;
    if (i < Bn * Nn) g_maskf[i] = mask[i] ? -1e30f : 0.0f;
}

__global__ void prep_split_x(const float4* __restrict__ src) {
    int i = blockIdx.x * blockDim.x + threadIdx.x;      // over MT*Dn/4
    float4 v = src[i];
    float r0, r1, r2, r3;
    uint32_t h0 = packh_hi(v.x, v.y, r0, r1);
    uint32_t h1 = packh_hi(v.z, v.w, r2, r3);
    reinterpret_cast<uint2*>(g_xh)[i] = make_uint2(h0, h1);
    reinterpret_cast<uint2*>(g_xl)[i] = make_uint2(packh(r0, r1), packh(r2, r3));
}

__global__ void prep_round_w(const float4* __restrict__ w0, const float4* __restrict__ w1,
                             const float4* __restrict__ w2, const float4* __restrict__ w3) {
    int i = blockIdx.x * blockDim.x + threadIdx.x;      // over Dn*Dn/4
    int z = blockIdx.y;
    const float4* src = (z == 0) ? w0 : (z == 1) ? w1 : (z == 2) ? w2 : w3;
    float4 v = src[i];
    reinterpret_cast<uint2*>(g_wh)[(size_t)z * (Dn * Dn / 4) + i] =
        make_uint2(packh(v.x, v.y), packh(v.z, v.w));
}

// ===========================================================================
// fp16x2 GEMM (A = hi+lo, B = hi): CTA 256x128, 8 warps 4(m)x2(n), BK=32.
// ===========================================================================
#define BK    32
#define SAstr 40                    // fp16 elems per smem row (80 B)
#define GA_AH 0
#define GA_AL 20480                 // 256*80
#define GA_BH 40960                 // +256*80
#define GSTG  51200                 // + 128*80
#define SMEM_GEMM (2*GSTG)          // 102400 B
#define NCH   (Dn/BK)               // 16

#define GEMM_MAINLOOP(AH, AL, BH, ACC) \
    const uint32_t sU = smem_u32(smg); \
    const __half* Ah_g = (AH) + (size_t)m0 * Dn; \
    const __half* Al_g = (AL) + (size_t)m0 * Dn; \
    const __half* Bh_g = (BH) + (size_t)n0 * Dn; \
    auto prefetch = [&](int kc) { \
        const uint32_t u = sU + (kc & 1) * GSTG; \
        _Pragma("unroll") \
        for (int t = 0; t < 4; t++) { \
            int id = tid + t * 256; \
            int row = id >> 2, c = id & 3; \
            size_t go = (size_t)row * Dn + kc * BK + c * 8; \
            uint32_t so = u + row * (SAstr * 2) + c * 16; \
            cp16(so + GA_AH, Ah_g + go); \
            cp16(so + GA_AL, Al_g + go); \
        } \
        _Pragma("unroll") \
        for (int t = 0; t < 2; t++) { \
            int id = tid + t * 256; \
            int row = id >> 2, c = id & 3; \
            size_t go = (size_t)row * Dn + kc * BK + c * 8; \
            uint32_t so = u + row * (SAstr * 2) + c * 16; \
            cp16(so + GA_BH, Bh_g + go); \
        } \
        cp_commit(); \
    }; \
    prefetch(0); \
    _Pragma("unroll 1") \
    for (int kc = 0; kc < NCH; kc++) { \
        if (kc + 1 < NCH) { prefetch(kc + 1); cp_wait1(); } else { cp_wait0(); } \
        __syncthreads(); \
        const uint32_t s = sU + (kc & 1) * GSTG; \
        _Pragma("unroll") \
        for (int ks = 0; ks < 2; ks++) { \
            const int k0 = ks * 16; \
            uint32_t ah[4][4], al[4][4]; \
            _Pragma("unroll") \
            for (int t = 0; t < 4; t++) { \
                uint32_t ra = wm + t * 16 + (lane & 15); \
                uint32_t ad = s + (ra * SAstr + k0 + (lane >> 4) * 8) * 2; \
                ldm_x4(ah[t], ad + GA_AH); \
                ldm_x4(al[t], ad + GA_AL); \
            } \
            _Pragma("unroll") \
            for (int jj = 0; jj < 4; jj++) { \
                uint32_t rb = wn + 8 * (2 * jj + ((lane >> 4) & 1)) + (lane & 7); \
                uint32_t ad = s + (rb * SAstr + k0 + ((lane >> 3) & 1) * 8) * 2; \
                uint32_t bh[4]; \
                ldm_x4(bh, ad + GA_BH); \
                _Pragma("unroll") \
                for (int t = 0; t < 4; t++) { \
                    mma_f16(ACC[t][2 * jj],     ah[t], &bh[0]); \
                    mma_f16(ACC[t][2 * jj],     al[t], &bh[0]); \
                    mma_f16(ACC[t][2 * jj + 1], ah[t], &bh[2]); \
                    mma_f16(ACC[t][2 * jj + 1], al[t], &bh[2]); \
                } \
            } \
        } \
        __syncthreads(); \
    }

// fp16x1 GEMM mainloop (A = hi only, B = hi) for the output projection.
#define G1_AH 0
#define G1_BH 20480                 // 256*80
#define G1STG 30720                 // +128*80
#define SMEM_GEMM1 (2*G1STG)        // 61440 B

#define GEMM_MAINLOOP1(AH, BH, ACC) \
    const uint32_t sU = smem_u32(smg); \
    const __half* Ah_g = (AH) + (size_t)m0 * Dn; \
    const __half* Bh_g = (BH) + (size_t)n0 * Dn; \
    auto prefetch = [&](int kc) { \
        const uint32_t u = sU + (kc & 1) * G1STG; \
        _Pragma("unroll") \
        for (int t = 0; t < 4; t++) { \
            int id = tid + t * 256; \
            int row = id >> 2, c = id & 3; \
            size_t go = (size_t)row * Dn + kc * BK + c * 8; \
            cp16(u + G1_AH + row * (SAstr * 2) + c * 16, Ah_g + go); \
        } \
        _Pragma("unroll") \
        for (int t = 0; t < 2; t++) { \
            int id = tid + t * 256; \
            int row = id >> 2, c = id & 3; \
            size_t go = (size_t)row * Dn + kc * BK + c * 8; \
            cp16(u + G1_BH + row * (SAstr * 2) + c * 16, Bh_g + go); \
        } \
        cp_commit(); \
    }; \
    prefetch(0); \
    _Pragma("unroll 1") \
    for (int kc = 0; kc < NCH; kc++) { \
        if (kc + 1 < NCH) { prefetch(kc + 1); cp_wait1(); } else { cp_wait0(); } \
        __syncthreads(); \
        const uint32_t s = sU + (kc & 1) * G1STG; \
        _Pragma("unroll") \
        for (int ks = 0; ks < 2; ks++) { \
            const int k0 = ks * 16; \
            uint32_t ah[4][4]; \
            _Pragma("unroll") \
            for (int t = 0; t < 4; t++) { \
                uint32_t ra = wm + t * 16 + (lane & 15); \
                ldm_x4(ah[t], s + G1_AH + (ra * SAstr + k0 + (lane >> 4) * 8) * 2); \
            } \
            _Pragma("unroll") \
            for (int jj = 0; jj < 4; jj++) { \
                uint32_t rb = wn + 8 * (2 * jj + ((lane >> 4) & 1)) + (lane & 7); \
                uint32_t bh[4]; \
                ldm_x4(bh, s + G1_BH + (rb * SAstr + k0 + ((lane >> 3) & 1) * 8) * 2); \
                _Pragma("unroll") \
                for (int t = 0; t < 4; t++) { \
                    mma_f16(ACC[t][2 * jj],     ah[t], &bh[0]); \
                    mma_f16(ACC[t][2 * jj + 1], ah[t], &bh[2]); \
                } \
            } \
        } \
        __syncthreads(); \
    }

// ---------------------------------------------------------------------------
// QKV projection GEMM: z=0 Q (scaled 1/8, split), z=1 K (hi only),
// z=2 V (smem-transposed, hi only)
// ---------------------------------------------------------------------------
#define TSTR2 264    // V-transpose smem: tokens per d-row (528 B, 16B-mult)

__global__ __launch_bounds__(256, 1) void gemm_qkv() {
    extern __shared__ __align__(16) char smg[];
    const int tid  = threadIdx.x;
    const int lane = tid & 31;
    const int g    = lane >> 2;
    const int tg   = lane & 3;
    const int wid  = tid >> 5;
    const int n0 = blockIdx.x * 128, m0 = blockIdx.y * 256;
    const int z  = blockIdx.z;
    const int wm = (wid & 3) * 64;     // 4 warps along M (256)
    const int wn = (wid >> 2) * 64;    // 2 warps along N (128)

    float acc[4][8][4];
    #pragma unroll
    for (int t = 0; t < 4; t++)
        #pragma unroll
        for (int j = 0; j < 8; j++)
            #pragma unroll
            for (int e = 0; e < 4; e++) acc[t][j][e] = 0.0f;

    const __half* Wh = g_wh + (size_t)z * Dn * Dn;
    GEMM_MAINLOOP(g_xh, g_xl, Wh, acc)

    if (z == 0) {
        // Q: scale 1/8, split hi/lo (A-side of S)
        #pragma unroll
        for (int t = 0; t < 4; t++)
            #pragma unroll
            for (int j = 0; j < 8; j++) {
                int r = m0 + wm + t * 16 + g;
                int c = n0 + wn + j * 8 + tg * 2;
                float v0 = acc[t][j][0] * 0.125f, v1 = acc[t][j][1] * 0.125f;
                float v2 = acc[t][j][2] * 0.125f, v3 = acc[t][j][3] * 0.125f;
                uint32_t h, l;
                packhl(v0, v1, h, l);
                *reinterpret_cast<uint32_t*>(&g_qh[(size_t)r * Dn + c]) = h;
                *reinterpret_cast<uint32_t*>(&g_ql[(size_t)r * Dn + c]) = l;
                packhl(v2, v3, h, l);
                *reinterpret_cast<uint32_t*>(&g_qh[(size_t)(r + 8) * Dn + c]) = h;
                *reinterpret_cast<uint32_t*>(&g_ql[(size_t)(r + 8) * Dn + c]) = l;
            }
    } else if (z == 1) {
        // K: hi only (B-side of S)
        #pragma unroll
        for (int t = 0; t < 4; t++)
            #pragma unroll
            for (int j = 0; j < 8; j++) {
                int r = m0 + wm + t * 16 + g;
                int c = n0 + wn + j * 8 + tg * 2;
                *reinterpret_cast<uint32_t*>(&g_kh[(size_t)r * Dn + c]) =
                    packh(acc[t][j][0], acc[t][j][1]);
                *reinterpret_cast<uint32_t*>(&g_kh[(size_t)(r + 8) * Dn + c]) =
                    packh(acc[t][j][2], acc[t][j][3]);
            }
    } else {
        // V: transpose through smem (hi only), coalesced out
        #pragma unroll
        for (int t = 0; t < 4; t++)
            #pragma unroll
            for (int j = 0; j < 8; j++)
                #pragma unroll
                for (int e = 0; e < 4; e++) {
                    int lr = wm + t * 16 + g + (e >> 1) * 8;   // local token 0..255
                    int lc = wn + j * 8 + tg * 2 + (e & 1);    // local dim 0..127
                    *reinterpret_cast<__half*>(smg + (size_t)lc * (TSTR2 * 2) + lr * 2) =
                        __float2half_rn(acc[t][j][e]);
                }
        __syncthreads();
        const int dd = tid >> 1;          // 0..127 (local dim)
        const int hf = tid & 1;           // token half (128 each)
        const int b  = m0 >> 11;
        const int hh = (n0 + dd) >> 6;
        const int d  = (n0 + dd) & 63;
        const size_t dst = (((size_t)(b * Hn + hh)) * HDn + d) * Nn + (m0 & (Nn - 1)) + hf * 128;
        const uint32_t so = (uint32_t)dd * (TSTR2 * 2) + hf * 256;
        #pragma unroll
        for (int u = 0; u < 16; u++)
            *reinterpret_cast<uint4*>(&g_vth[dst + u * 8]) =
                *reinterpret_cast<const uint4*>(smg + so + u * 16);
    }
}

// ---------------------------------------------------------------------------
// Output projection GEMM: O hi (A-side) x Wo hi (B-side), writes fp32
// ---------------------------------------------------------------------------
__global__ __launch_bounds__(256, 1) void gemm_out(float* __restrict__ C) {
    extern __shared__ __align__(16) char smg[];
    const int tid  = threadIdx.x;
    const int lane = tid & 31;
    const int g    = lane >> 2;
    const int tg   = lane & 3;
    const int wid  = tid >> 5;
    const int n0 = blockIdx.x * 128, m0 = blockIdx.y * 256;
    const int wm = (wid & 3) * 64;
    const int wn = (wid >> 2) * 64;

    float acc[4][8][4];
    #pragma unroll
    for (int t = 0; t < 4; t++)
        #pragma unroll
        for (int j = 0; j < 8; j++)
            #pragma unroll
            for (int e = 0; e < 4; e++) acc[t][j][e] = 0.0f;

    const __half* Wh = g_wh + (size_t)3 * Dn * Dn;
    GEMM_MAINLOOP1(g_oh, Wh, acc)

    #pragma unroll
    for (int t = 0; t < 4; t++)
        #pragma unroll
        for (int j = 0; j < 8; j++) {
            int row = m0 + wm + t * 16 + g;
            int col = n0 + wn + j * 8 + tg * 2;
            *reinterpret_cast<float2*>(C + (size_t)row * Dn + col) =
                make_float2(acc[t][j][0], acc[t][j][1]);
            *reinterpret_cast<float2*>(C + (size_t)(row + 8) * Dn + col) =
                make_float2(acc[t][j][2], acc[t][j][3]);
        }
}

// ===========================================================================
// Tensor-core flash attention: 128 q-rows per CTA (8 warps x 16 rows),
// k-tiles of 64 keys. S = (qh+ql)·kh (x2); PV = ph·vh (x1, incoherent error).
// cp.async double buffer, 2 CTAs/SM.
// ===========================================================================
#define KSTR 144
#define VSTR 144
#define KARR (64*KSTR)                // 9216 (K hi)
#define VOFF KARR                     // V hi at +9216
#define MOFF (2*KARR)                 // mask at +18432
#define STG_ATT (MOFF + 256)          // 18688
#define SMEM_ATT (2*STG_ATT)          // 37376

__global__ __launch_bounds__(256, 2) void attn_mma(const float* __restrict__ bias) {
    extern __shared__ __align__(16) char sma[];
    const uint32_t sb = smem_u32(sma);
    const int tid  = threadIdx.x;
    const int lane = tid & 31;
    const int w    = tid >> 5;
    const int g    = lane >> 2;
    const int tg   = lane & 3;
    const int h  = blockIdx.x;
    const int q0 = blockIdx.y * 128;
    const int b  = blockIdx.z;

    // ---- Q fragments from gmem (once) ----
    uint32_t qh[4][4], ql[4][4];
    {
        const size_t rbase = (size_t)(b * Nn + q0 + w * 16) * Dn + h * HDn;
        #pragma unroll
        for (int c = 0; c < 4; c++) {
            size_t o0 = rbase + (size_t)g * Dn + c * 16 + tg * 2;
            size_t o1 = rbase + (size_t)(g + 8) * Dn + c * 16 + tg * 2;
            qh[c][0] = *reinterpret_cast<const uint32_t*>(&g_qh[o0]);
            qh[c][1] = *reinterpret_cast<const uint32_t*>(&g_qh[o1]);
            qh[c][2] = *reinterpret_cast<const uint32_t*>(&g_qh[o0 + 8]);
            qh[c][3] = *reinterpret_cast<const uint32_t*>(&g_qh[o1 + 8]);
            ql[c][0] = *reinterpret_cast<const uint32_t*>(&g_ql[o0]);
            ql[c][1] = *reinterpret_cast<const uint32_t*>(&g_ql[o1]);
            ql[c][2] = *reinterpret_cast<const uint32_t*>(&g_ql[o0 + 8]);
            ql[c][3] = *reinterpret_cast<const uint32_t*>(&g_ql[o1 + 8]);
        }
    }

    const char* kh_base = (const char*)g_kh + ((size_t)(b * Nn) * Dn + h * HDn) * 2;
    const char* vh_base = (const char*)g_vth + ((size_t)(b * Hn + h) * HDn) * Nn * 2;
    const char* mk_base = (const char*)g_maskf + (size_t)(b * Nn) * 4;

    auto prefetch = [&](int kt) {
        const uint32_t u = sb + (kt & 1) * STG_ATT;
        const size_t kof = (size_t)kt * 64 * (Dn * 2);
        #pragma unroll
        for (int t = 0; t < 2; t++) {
            int id = tid + t * 256;           // 512 = 64 rows x 8 chunks
            int row = id >> 3, c = id & 7;
            cp16(u + row * KSTR + c * 16,        kh_base + kof + (size_t)row * (Dn * 2) + c * 16);
            cp16(u + VOFF + row * VSTR + c * 16,
                 vh_base + (size_t)row * (Nn * 2) + kt * 128 + c * 16);
        }
        if (tid < 16) cp16(u + MOFF + tid * 16, mk_base + (size_t)kt * 256 + tid * 16);
        cp_commit();
    };

    float O[8][4];
    #pragma unroll
    for (int j = 0; j < 8; j++)
        #pragma unroll
        for (int e = 0; e < 4; e++) O[j][e] = 0.0f;
    float m0r = -3e38f, m1r = -3e38f, l0 = 0.0f, l1 = 0.0f;

    prefetch(0);

    const float* bb = bias + ((size_t)(b * Nn) + q0 + w * 16) * Nn;

    #pragma unroll 1
    for (int kt = 0; kt < Nn / 64; kt++) {
        cp_wait0();
        __syncthreads();
        const uint32_t u = sb + (kt & 1) * STG_ATT;
        if (kt + 1 < Nn / 64) prefetch(kt + 1);

        // ---- S = Q K^T (fp16x2: qh+ql vs kh) ----
        float Sf[8][4];
        #pragma unroll
        for (int j = 0; j < 8; j++)
            #pragma unroll
            for (int e = 0; e < 4; e++) Sf[j][e] = 0.0f;

        #pragma unroll
        for (int c = 0; c < 4; c++) {
            #pragma unroll
            for (int jp = 0; jp < 4; jp++) {
                const int mrow = 8 * (2 * jp + ((lane >> 4) & 1)) + (lane & 7);
                const int mcol = 16 * c + ((lane >> 3) & 1) * 8;
                const uint32_t ad = u + mrow * KSTR + mcol * 2;
                uint32_t bh[4];
                ldm_x4(bh, ad);
                mma_f16(Sf[2 * jp],     qh[c], &bh[0]);
                mma_f16(Sf[2 * jp],     ql[c], &bh[0]);
                mma_f16(Sf[2 * jp + 1], qh[c], &bh[2]);
                mma_f16(Sf[2 * jp + 1], ql[c], &bh[2]);
            }
        }

        // ---- bias + mask ----
        const float* bt = bb + (size_t)kt * 64;
        #pragma unroll
        for (int j = 0; j < 8; j++) {
            float2 mv = *reinterpret_cast<const float2*>(sma + (kt & 1) * STG_ATT + MOFF
                                                         + (8 * j + 2 * tg) * 4);
            float2 bv0 = *reinterpret_cast<const float2*>(bt + (size_t)g * Nn + 8 * j + 2 * tg);
            float2 bv1 = *reinterpret_cast<const float2*>(bt + (size_t)(g + 8) * Nn + 8 * j + 2 * tg);
            Sf[j][0] += bv0.x + mv.x; Sf[j][1] += bv0.y + mv.y;
            Sf[j][2] += bv1.x + mv.x; Sf[j][3] += bv1.y + mv.y;
        }

        // ---- online softmax on fragments ----
        float mx0 = -3e38f, mx1 = -3e38f;
        #pragma unroll
        for (int j = 0; j < 8; j++) {
            mx0 = fmaxf(mx0, fmaxf(Sf[j][0], Sf[j][1]));
            mx1 = fmaxf(mx1, fmaxf(Sf[j][2], Sf[j][3]));
        }
        #pragma unroll
        for (int off = 1; off < 4; off <<= 1) {
            mx0 = fmaxf(mx0, __shfl_xor_sync(0xffffffffu, mx0, off));
            mx1 = fmaxf(mx1, __shfl_xor_sync(0xffffffffu, mx1, off));
        }
        const float mn0 = fmaxf(m0r, mx0), mn1 = fmaxf(m1r, mx1);
        const float sc0 = __expf(m0r - mn0), sc1 = __expf(m1r - mn1);
        m0r = mn0; m1r = mn1;
        float sum0 = 0.0f, sum1 = 0.0f;
        #pragma unroll
        for (int j = 0; j < 8; j++) {
            Sf[j][0] = __expf(Sf[j][0] - mn0);
            Sf[j][1] = __expf(Sf[j][1] - mn0);
            Sf[j][2] = __expf(Sf[j][2] - mn1);
            Sf[j][3] = __expf(Sf[j][3] - mn1);
            sum0 += Sf[j][0] + Sf[j][1];
            sum1 += Sf[j][2] + Sf[j][3];
        }
        #pragma unroll
        for (int off = 1; off < 4; off <<= 1) {
            sum0 += __shfl_xor_sync(0xffffffffu, sum0, off);
            sum1 += __shfl_xor_sync(0xffffffffu, sum1, off);
        }
        l0 = l0 * sc0 + sum0;
        l1 = l1 * sc1 + sum1;
        #pragma unroll
        for (int j = 0; j < 8; j++) {
            O[j][0] *= sc0; O[j][1] *= sc0;
            O[j][2] *= sc1; O[j][3] *= sc1;
        }

        // ---- O += P V (fp16x1: ph vs vh; P rounding is incoherent over keys) ----
        const uint32_t uV = u + VOFF;
        #pragma unroll
        for (int c = 0; c < 4; c++) {
            uint32_t ph[4];
            ph[0] = packh(Sf[2 * c][0],     Sf[2 * c][1]);
            ph[1] = packh(Sf[2 * c][2],     Sf[2 * c][3]);
            ph[2] = packh(Sf[2 * c + 1][0], Sf[2 * c + 1][1]);
            ph[3] = packh(Sf[2 * c + 1][2], Sf[2 * c + 1][3]);
            #pragma unroll
            for (int jp = 0; jp < 4; jp++) {
                const int mrow = 8 * (2 * jp + ((lane >> 4) & 1)) + (lane & 7);
                const int mcol = 16 * c + ((lane >> 3) & 1) * 8;
                const uint32_t ad = uV + mrow * VSTR + mcol * 2;
                uint32_t vh[4];
                ldm_x4(vh, ad);
                mma_f16(O[2 * jp],     ph, &vh[0]);
                mma_f16(O[2 * jp + 1], ph, &vh[2]);
            }
        }
    }

    // ---- normalize + write hi fp16 (A-side of out proj) ----
    const float inv0 = 1.0f / l0, inv1 = 1.0f / l1;
    const size_t rbase = (size_t)(b * Nn + q0 + w * 16) * Dn + h * HDn;
    #pragma unroll
    for (int j = 0; j < 8; j++) {
        const int col = 8 * j + 2 * tg;
        *reinterpret_cast<uint32_t*>(&g_oh[rbase + (size_t)g * Dn + col]) =
            packh(O[j][0] * inv0, O[j][1] * inv0);
        *reinterpret_cast<uint32_t*>(&g_oh[rbase + (size_t)(g + 8) * Dn + col]) =
            packh(O[j][2] * inv1, O[j][3] * inv1);
    }
}

// ---------------------------------------------------------------------------
// Launch. Inputs (metadata order): q, mask, attn_bias, Wq, Wk, Wv, Wo
// ---------------------------------------------------------------------------
extern "C" void kernel_launch(void* const* d_in, const int* in_sizes, int n_in,
                              void* d_out, int out_size) {
    const float* q    = (const float*)d_in[0];
    const int*   mask = (const int*)d_in[1];
    const float* bias = (const float*)d_in[2];
    const float* Wq   = (const float*)d_in[3];
    const float* Wk   = (const float*)d_in[4];
    const float* Wv   = (const float*)d_in[5];
    const float* Wo   = (const float*)d_in[6];
    float* out = (float*)d_out;

    cudaFuncSetAttribute(gemm_qkv, cudaFuncAttributeMaxDynamicSharedMemorySize, SMEM_GEMM);
    cudaFuncSetAttribute(gemm_out, cudaFuncAttributeMaxDynamicSharedMemorySize, SMEM_GEMM1);
    cudaFuncSetAttribute(attn_mma, cudaFuncAttributeMaxDynamicSharedMemorySize, SMEM_ATT);

    mask_prep<<<32, 256>>>(mask);
    prep_split_x<<<MT * Dn / 4 / 256, 256>>>((const float4*)q);
    prep_round_w<<<dim3(Dn * Dn / 4 / 256, 4), 256>>>(
        (const float4*)Wq, (const float4*)Wk, (const float4*)Wv, (const float4*)Wo);

    gemm_qkv<<<dim3(Dn / 128, MT / 256, 3), 256, SMEM_GEMM>>>();

    attn_mma<<<dim3(Hn, Nn / 128, Bn), 256, SMEM_ATT>>>(bias);

    gemm_out<<<dim3(Dn / 128, MT / 256, 1), 256, SMEM_GEMM1>>>(out);
}

// round 16
// speedup vs baseline: 3.0952x; 1.1733x over previous
#include <cuda_runtime.h>
#include <cuda_fp16.h>
#include <cstdint>

// Problem constants
#define Bn  4
#define Nn  2048
#define Dn  512
#define Hn  8
#define HDn 64
#define MT  (Bn*Nn)   // 8192 rows

// Scratch (allocation-free rule: __device__ globals) — fp16 everywhere.
// All rounding errors are incoherent over their contraction dims (~2.4e-4 each,
// ~7 sources RSS => ~7e-4 < 1e-3).
__device__ __half g_xh[MT*Dn];                        // input q rounded
__device__ __half g_wh[4*Dn*Dn];                      // Wq,Wk,Wv,Wo rounded
__device__ __half g_qh[MT*Dn];                        // Q proj (scaled 1/8)
__device__ __half g_kh[MT*Dn];                        // K proj [tok][dim]
__device__ __half g_vth[MT*Dn];                       // V proj transposed [(b,h,d)][tok]
__device__ __half g_oh[MT*Dn];                        // attention output
__device__ float g_maskf[Bn*Nn];

// ===========================================================================
// common helpers
// ===========================================================================
__device__ __forceinline__ uint32_t smem_u32(const void* p) {
    uint32_t a;
    asm("{ .reg .u64 t; cvta.to.shared.u64 t, %1; cvt.u32.u64 %0, t; }" : "=r"(a) : "l"(p));
    return a;
}
__device__ __forceinline__ void mma_f16(float* c, const uint32_t* a, const uint32_t* b) {
    asm volatile("mma.sync.aligned.m16n8k16.row.col.f32.f16.f16.f32 "
        "{%0,%1,%2,%3}, {%4,%5,%6,%7}, {%8,%9}, {%0,%1,%2,%3};"
        : "+f"(c[0]), "+f"(c[1]), "+f"(c[2]), "+f"(c[3])
        : "r"(a[0]), "r"(a[1]), "r"(a[2]), "r"(a[3]), "r"(b[0]), "r"(b[1]));
}
__device__ __forceinline__ void ldm_x4(uint32_t* r, uint32_t saddr) {
    asm volatile("ldmatrix.sync.aligned.m8n8.x4.shared.b16 {%0,%1,%2,%3}, [%4];"
        : "=r"(r[0]), "=r"(r[1]), "=r"(r[2]), "=r"(r[3]) : "r"(saddr));
}
__device__ __forceinline__ void cp16(uint32_t saddr, const void* g) {
    asm volatile("cp.async.ca.shared.global [%0], [%1], 16;" :: "r"(saddr), "l"(g));
}
__device__ __forceinline__ void cp_commit() { asm volatile("cp.async.commit_group;" ::: "memory"); }
__device__ __forceinline__ void cp_wait0()  { asm volatile("cp.async.wait_group 0;" ::: "memory"); }
__device__ __forceinline__ void cp_wait1()  { asm volatile("cp.async.wait_group 1;" ::: "memory"); }

__device__ __forceinline__ uint32_t packh(float x, float y) {
    return (uint32_t)__half_as_ushort(__float2half_rn(x)) |
           ((uint32_t)__half_as_ushort(__float2half_rn(y)) << 16);
}

// ===========================================================================
// prep: mask -> float addend; fp32 -> fp16 rounding
// ===========================================================================
__global__ void mask_prep(const int* __restrict__ mask) {
    int i = blockIdx.x * blockDim.x + threadIdx.x;
    if (i < Bn * Nn) g_maskf[i] = mask[i] ? -1e30f : 0.0f;
}

__global__ void prep_round_x(const float4* __restrict__ src) {
    int i = blockIdx.x * blockDim.x + threadIdx.x;      // over MT*Dn/4
    float4 v = src[i];
    reinterpret_cast<uint2*>(g_xh)[i] = make_uint2(packh(v.x, v.y), packh(v.z, v.w));
}

__global__ void prep_round_w(const float4* __restrict__ w0, const float4* __restrict__ w1,
                             const float4* __restrict__ w2, const float4* __restrict__ w3) {
    int i = blockIdx.x * blockDim.x + threadIdx.x;      // over Dn*Dn/4
    int z = blockIdx.y;
    const float4* src = (z == 0) ? w0 : (z == 1) ? w1 : (z == 2) ? w2 : w3;
    float4 v = src[i];
    reinterpret_cast<uint2*>(g_wh)[(size_t)z * (Dn * Dn / 4) + i] =
        make_uint2(packh(v.x, v.y), packh(v.z, v.w));
}

// ===========================================================================
// fp16x1 GEMM: CTA 256x128, 8 warps 4(m)x2(n), warp tile 64x64, BK=32,
// 2-stage cp.async, ldmatrix.
// ===========================================================================
#define BK    32
#define SAstr 40                    // fp16 elems per smem row (80 B)
#define G1_AH 0
#define G1_BH 20480                 // 256*80
#define G1STG 30720                 // +128*80
#define SMEM_GEMM1 (2*G1STG)        // 61440 B
#define NCH   (Dn/BK)               // 16

// V-transpose epilogue scratch: 128 dims x TSTR2 tokens x 2B = 67584 B.
// gemm_qkv must allocate the max of mainloop and transpose footprints.
#define TSTR2 264
#define SMEM_VT (128*TSTR2*2)       // 67584 B
#define SMEM_QKV (SMEM_VT > SMEM_GEMM1 ? SMEM_VT : SMEM_GEMM1)   // 67584 B

#define GEMM_MAINLOOP1(AH, BH, ACC) \
    const uint32_t sU = smem_u32(smg); \
    const __half* Ah_g = (AH) + (size_t)m0 * Dn; \
    const __half* Bh_g = (BH) + (size_t)n0 * Dn; \
    auto prefetch = [&](int kc) { \
        const uint32_t u = sU + (kc & 1) * G1STG; \
        _Pragma("unroll") \
        for (int t = 0; t < 4; t++) {                /* A: 256 rows x 4 chunks */ \
            int id = tid + t * 256; \
            int row = id >> 2, c = id & 3; \
            size_t go = (size_t)row * Dn + kc * BK + c * 8; \
            cp16(u + G1_AH + row * (SAstr * 2) + c * 16, Ah_g + go); \
        } \
        _Pragma("unroll") \
        for (int t = 0; t < 2; t++) {                /* B: 128 rows x 4 chunks */ \
            int id = tid + t * 256; \
            int row = id >> 2, c = id & 3; \
            size_t go = (size_t)row * Dn + kc * BK + c * 8; \
            cp16(u + G1_BH + row * (SAstr * 2) + c * 16, Bh_g + go); \
        } \
        cp_commit(); \
    }; \
    prefetch(0); \
    _Pragma("unroll 1") \
    for (int kc = 0; kc < NCH; kc++) { \
        if (kc + 1 < NCH) { prefetch(kc + 1); cp_wait1(); } else { cp_wait0(); } \
        __syncthreads(); \
        const uint32_t s = sU + (kc & 1) * G1STG; \
        _Pragma("unroll") \
        for (int ks = 0; ks < 2; ks++) { \
            const int k0 = ks * 16; \
            uint32_t ah[4][4]; \
            _Pragma("unroll") \
            for (int t = 0; t < 4; t++) { \
                uint32_t ra = wm + t * 16 + (lane & 15); \
                ldm_x4(ah[t], s + G1_AH + (ra * SAstr + k0 + (lane >> 4) * 8) * 2); \
            } \
            _Pragma("unroll") \
            for (int jj = 0; jj < 4; jj++) { \
                uint32_t rb = wn + 8 * (2 * jj + ((lane >> 4) & 1)) + (lane & 7); \
                uint32_t bh[4]; \
                ldm_x4(bh, s + G1_BH + (rb * SAstr + k0 + ((lane >> 3) & 1) * 8) * 2); \
                _Pragma("unroll") \
                for (int t = 0; t < 4; t++) { \
                    mma_f16(ACC[t][2 * jj],     ah[t], &bh[0]); \
                    mma_f16(ACC[t][2 * jj + 1], ah[t], &bh[2]); \
                } \
            } \
        } \
        __syncthreads(); \
    }

// ---------------------------------------------------------------------------
// QKV projection GEMM: z=0 Q (scaled 1/8), z=1 K, z=2 V (smem-transposed)
// ---------------------------------------------------------------------------
__global__ __launch_bounds__(256, 1) void gemm_qkv() {
    extern __shared__ __align__(16) char smg[];
    const int tid  = threadIdx.x;
    const int lane = tid & 31;
    const int g    = lane >> 2;
    const int tg   = lane & 3;
    const int wid  = tid >> 5;
    const int n0 = blockIdx.x * 128, m0 = blockIdx.y * 256;
    const int z  = blockIdx.z;
    const int wm = (wid & 3) * 64;     // 4 warps along M (256)
    const int wn = (wid >> 2) * 64;    // 2 warps along N (128)

    float acc[4][8][4];
    #pragma unroll
    for (int t = 0; t < 4; t++)
        #pragma unroll
        for (int j = 0; j < 8; j++)
            #pragma unroll
            for (int e = 0; e < 4; e++) acc[t][j][e] = 0.0f;

    const __half* Wh = g_wh + (size_t)z * Dn * Dn;
    GEMM_MAINLOOP1(g_xh, Wh, acc)

    if (z == 0) {
        // Q: scale 1/8
        #pragma unroll
        for (int t = 0; t < 4; t++)
            #pragma unroll
            for (int j = 0; j < 8; j++) {
                int r = m0 + wm + t * 16 + g;
                int c = n0 + wn + j * 8 + tg * 2;
                *reinterpret_cast<uint32_t*>(&g_qh[(size_t)r * Dn + c]) =
                    packh(acc[t][j][0] * 0.125f, acc[t][j][1] * 0.125f);
                *reinterpret_cast<uint32_t*>(&g_qh[(size_t)(r + 8) * Dn + c]) =
                    packh(acc[t][j][2] * 0.125f, acc[t][j][3] * 0.125f);
            }
    } else if (z == 1) {
        // K
        #pragma unroll
        for (int t = 0; t < 4; t++)
            #pragma unroll
            for (int j = 0; j < 8; j++) {
                int r = m0 + wm + t * 16 + g;
                int c = n0 + wn + j * 8 + tg * 2;
                *reinterpret_cast<uint32_t*>(&g_kh[(size_t)r * Dn + c]) =
                    packh(acc[t][j][0], acc[t][j][1]);
                *reinterpret_cast<uint32_t*>(&g_kh[(size_t)(r + 8) * Dn + c]) =
                    packh(acc[t][j][2], acc[t][j][3]);
            }
    } else {
        // V: transpose through smem, coalesced out.
        // Mainloop is done (final __syncthreads issued); smem is reusable.
        __syncthreads();
        #pragma unroll
        for (int t = 0; t < 4; t++)
            #pragma unroll
            for (int j = 0; j < 8; j++)
                #pragma unroll
                for (int e = 0; e < 4; e++) {
                    int lr = wm + t * 16 + g + (e >> 1) * 8;   // local token 0..255
                    int lc = wn + j * 8 + tg * 2 + (e & 1);    // local dim 0..127
                    *reinterpret_cast<__half*>(smg + (size_t)lc * (TSTR2 * 2) + lr * 2) =
                        __float2half_rn(acc[t][j][e]);
                }
        __syncthreads();
        const int dd = tid >> 1;          // 0..127 (local dim)
        const int hf = tid & 1;           // token half (128 each)
        const int b  = m0 >> 11;
        const int hh = (n0 + dd) >> 6;
        const int d  = (n0 + dd) & 63;
        const size_t dst = (((size_t)(b * Hn + hh)) * HDn + d) * Nn + (m0 & (Nn - 1)) + hf * 128;
        const uint32_t so = (uint32_t)dd * (TSTR2 * 2) + hf * 256;
        #pragma unroll
        for (int u = 0; u < 16; u++)
            *reinterpret_cast<uint4*>(&g_vth[dst + u * 8]) =
                *reinterpret_cast<const uint4*>(smg + so + u * 16);
    }
}

// ---------------------------------------------------------------------------
// Output projection GEMM: O x Wo, writes fp32
// ---------------------------------------------------------------------------
__global__ __launch_bounds__(256, 1) void gemm_out(float* __restrict__ C) {
    extern __shared__ __align__(16) char smg[];
    const int tid  = threadIdx.x;
    const int lane = tid & 31;
    const int g    = lane >> 2;
    const int tg   = lane & 3;
    const int wid  = tid >> 5;
    const int n0 = blockIdx.x * 128, m0 = blockIdx.y * 256;
    const int wm = (wid & 3) * 64;
    const int wn = (wid >> 2) * 64;

    float acc[4][8][4];
    #pragma unroll
    for (int t = 0; t < 4; t++)
        #pragma unroll
        for (int j = 0; j < 8; j++)
            #pragma unroll
            for (int e = 0; e < 4; e++) acc[t][j][e] = 0.0f;

    const __half* Wh = g_wh + (size_t)3 * Dn * Dn;
    GEMM_MAINLOOP1(g_oh, Wh, acc)

    #pragma unroll
    for (int t = 0; t < 4; t++)
        #pragma unroll
        for (int j = 0; j < 8; j++) {
            int row = m0 + wm + t * 16 + g;
            int col = n0 + wn + j * 8 + tg * 2;
            *reinterpret_cast<float2*>(C + (size_t)row * Dn + col) =
                make_float2(acc[t][j][0], acc[t][j][1]);
            *reinterpret_cast<float2*>(C + (size_t)(row + 8) * Dn + col) =
                make_float2(acc[t][j][2], acc[t][j][3]);
        }
}

// ===========================================================================
// Tensor-core flash attention: 128 q-rows per CTA (8 warps x 16 rows),
// k-tiles of 64 keys, all fp16x1, cp.async double buffer, 2 CTAs/SM.
// ===========================================================================
#define KSTR 144
#define VSTR 144
#define KARR (64*KSTR)                // 9216 (K)
#define VOFF KARR                     // V at +9216
#define MOFF (2*KARR)                 // mask at +18432
#define STG_ATT (MOFF + 256)          // 18688
#define SMEM_ATT (2*STG_ATT)          // 37376

__global__ __launch_bounds__(256, 2) void attn_mma(const float* __restrict__ bias) {
    extern __shared__ __align__(16) char sma[];
    const uint32_t sb = smem_u32(sma);
    const int tid  = threadIdx.x;
    const int lane = tid & 31;
    const int w    = tid >> 5;
    const int g    = lane >> 2;
    const int tg   = lane & 3;
    const int h  = blockIdx.x;
    const int q0 = blockIdx.y * 128;
    const int b  = blockIdx.z;

    // ---- Q fragments from gmem (once) ----
    uint32_t qh[4][4];
    {
        const size_t rbase = (size_t)(b * Nn + q0 + w * 16) * Dn + h * HDn;
        #pragma unroll
        for (int c = 0; c < 4; c++) {
            size_t o0 = rbase + (size_t)g * Dn + c * 16 + tg * 2;
            size_t o1 = rbase + (size_t)(g + 8) * Dn + c * 16 + tg * 2;
            qh[c][0] = *reinterpret_cast<const uint32_t*>(&g_qh[o0]);
            qh[c][1] = *reinterpret_cast<const uint32_t*>(&g_qh[o1]);
            qh[c][2] = *reinterpret_cast<const uint32_t*>(&g_qh[o0 + 8]);
            qh[c][3] = *reinterpret_cast<const uint32_t*>(&g_qh[o1 + 8]);
        }
    }

    const char* kh_base = (const char*)g_kh + ((size_t)(b * Nn) * Dn + h * HDn) * 2;
    const char* vh_base = (const char*)g_vth + ((size_t)(b * Hn + h) * HDn) * Nn * 2;
    const char* mk_base = (const char*)g_maskf + (size_t)(b * Nn) * 4;

    auto prefetch = [&](int kt) {
        const uint32_t u = sb + (kt & 1) * STG_ATT;
        const size_t kof = (size_t)kt * 64 * (Dn * 2);
        #pragma unroll
        for (int t = 0; t < 2; t++) {
            int id = tid + t * 256;           // 512 = 64 rows x 8 chunks
            int row = id >> 3, c = id & 7;
            cp16(u + row * KSTR + c * 16,        kh_base + kof + (size_t)row * (Dn * 2) + c * 16);
            cp16(u + VOFF + row * VSTR + c * 16,
                 vh_base + (size_t)row * (Nn * 2) + kt * 128 + c * 16);
        }
        if (tid < 16) cp16(u + MOFF + tid * 16, mk_base + (size_t)kt * 256 + tid * 16);
        cp_commit();
    };

    float O[8][4];
    #pragma unroll
    for (int j = 0; j < 8; j++)
        #pragma unroll
        for (int e = 0; e < 4; e++) O[j][e] = 0.0f;
    float m0r = -3e38f, m1r = -3e38f, l0 = 0.0f, l1 = 0.0f;

    prefetch(0);

    const float* bb = bias + ((size_t)(b * Nn) + q0 + w * 16) * Nn;

    #pragma unroll 1
    for (int kt = 0; kt < Nn / 64; kt++) {
        cp_wait0();
        __syncthreads();
        const uint32_t u = sb + (kt & 1) * STG_ATT;
        if (kt + 1 < Nn / 64) prefetch(kt + 1);

        // ---- S = Q K^T (fp16x1) ----
        float Sf[8][4];
        #pragma unroll
        for (int j = 0; j < 8; j++)
            #pragma unroll
            for (int e = 0; e < 4; e++) Sf[j][e] = 0.0f;

        #pragma unroll
        for (int c = 0; c < 4; c++) {
            #pragma unroll
            for (int jp = 0; jp < 4; jp++) {
                const int mrow = 8 * (2 * jp + ((lane >> 4) & 1)) + (lane & 7);
                const int mcol = 16 * c + ((lane >> 3) & 1) * 8;
                const uint32_t ad = u + mrow * KSTR + mcol * 2;
                uint32_t bh[4];
                ldm_x4(bh, ad);
                mma_f16(Sf[2 * jp],     qh[c], &bh[0]);
                mma_f16(Sf[2 * jp + 1], qh[c], &bh[2]);
            }
        }

        // ---- bias + mask ----
        const float* bt = bb + (size_t)kt * 64;
        #pragma unroll
        for (int j = 0; j < 8; j++) {
            float2 mv = *reinterpret_cast<const float2*>(sma + (kt & 1) * STG_ATT + MOFF
                                                         + (8 * j + 2 * tg) * 4);
            float2 bv0 = *reinterpret_cast<const float2*>(bt + (size_t)g * Nn + 8 * j + 2 * tg);
            float2 bv1 = *reinterpret_cast<const float2*>(bt + (size_t)(g + 8) * Nn + 8 * j + 2 * tg);
            Sf[j][0] += bv0.x + mv.x; Sf[j][1] += bv0.y + mv.y;
            Sf[j][2] += bv1.x + mv.x; Sf[j][3] += bv1.y + mv.y;
        }

        // ---- online softmax on fragments ----
        float mx0 = -3e38f, mx1 = -3e38f;
        #pragma unroll
        for (int j = 0; j < 8; j++) {
            mx0 = fmaxf(mx0, fmaxf(Sf[j][0], Sf[j][1]));
            mx1 = fmaxf(mx1, fmaxf(Sf[j][2], Sf[j][3]));
        }
        #pragma unroll
        for (int off = 1; off < 4; off <<= 1) {
            mx0 = fmaxf(mx0, __shfl_xor_sync(0xffffffffu, mx0, off));
            mx1 = fmaxf(mx1, __shfl_xor_sync(0xffffffffu, mx1, off));
        }
        const float mn0 = fmaxf(m0r, mx0), mn1 = fmaxf(m1r, mx1);
        const float sc0 = __expf(m0r - mn0), sc1 = __expf(m1r - mn1);
        m0r = mn0; m1r = mn1;
        float sum0 = 0.0f, sum1 = 0.0f;
        #pragma unroll
        for (int j = 0; j < 8; j++) {
            Sf[j][0] = __expf(Sf[j][0] - mn0);
            Sf[j][1] = __expf(Sf[j][1] - mn0);
            Sf[j][2] = __expf(Sf[j][2] - mn1);
            Sf[j][3] = __expf(Sf[j][3] - mn1);
            sum0 += Sf[j][0] + Sf[j][1];
            sum1 += Sf[j][2] + Sf[j][3];
        }
        #pragma unroll
        for (int off = 1; off < 4; off <<= 1) {
            sum0 += __shfl_xor_sync(0xffffffffu, sum0, off);
            sum1 += __shfl_xor_sync(0xffffffffu, sum1, off);
        }
        l0 = l0 * sc0 + sum0;
        l1 = l1 * sc1 + sum1;
        #pragma unroll
        for (int j = 0; j < 8; j++) {
            O[j][0] *= sc0; O[j][1] *= sc0;
            O[j][2] *= sc1; O[j][3] *= sc1;
        }

        // ---- O += P V (fp16x1) ----
        const uint32_t uV = u + VOFF;
        #pragma unroll
        for (int c = 0; c < 4; c++) {
            uint32_t ph[4];
            ph[0] = packh(Sf[2 * c][0],     Sf[2 * c][1]);
            ph[1] = packh(Sf[2 * c][2],     Sf[2 * c][3]);
            ph[2] = packh(Sf[2 * c + 1][0], Sf[2 * c + 1][1]);
            ph[3] = packh(Sf[2 * c + 1][2], Sf[2 * c + 1][3]);
            #pragma unroll
            for (int jp = 0; jp < 4; jp++) {
                const int mrow = 8 * (2 * jp + ((lane >> 4) & 1)) + (lane & 7);
                const int mcol = 16 * c + ((lane >> 3) & 1) * 8;
                const uint32_t ad = uV + mrow * VSTR + mcol * 2;
                uint32_t vh[4];
                ldm_x4(vh, ad);
                mma_f16(O[2 * jp],     ph, &vh[0]);
                mma_f16(O[2 * jp + 1], ph, &vh[2]);
            }
        }
    }

    // ---- normalize + write fp16 ----
    const float inv0 = 1.0f / l0, inv1 = 1.0f / l1;
    const size_t rbase = (size_t)(b * Nn + q0 + w * 16) * Dn + h * HDn;
    #pragma unroll
    for (int j = 0; j < 8; j++) {
        const int col = 8 * j + 2 * tg;
        *reinterpret_cast<uint32_t*>(&g_oh[rbase + (size_t)g * Dn + col]) =
            packh(O[j][0] * inv0, O[j][1] * inv0);
        *reinterpret_cast<uint32_t*>(&g_oh[rbase + (size_t)(g + 8) * Dn + col]) =
            packh(O[j][2] * inv1, O[j][3] * inv1);
    }
}

// ---------------------------------------------------------------------------
// Launch. Inputs (metadata order): q, mask, attn_bias, Wq, Wk, Wv, Wo
// ---------------------------------------------------------------------------
extern "C" void kernel_launch(void* const* d_in, const int* in_sizes, int n_in,
                              void* d_out, int out_size) {
    const float* q    = (const float*)d_in[0];
    const int*   mask = (const int*)d_in[1];
    const float* bias = (const float*)d_in[2];
    const float* Wq   = (const float*)d_in[3];
    const float* Wk   = (const float*)d_in[4];
    const float* Wv   = (const float*)d_in[5];
    const float* Wo   = (const float*)d_in[6];
    float* out = (float*)d_out;

    cudaFuncSetAttribute(gemm_qkv, cudaFuncAttributeMaxDynamicSharedMemorySize, SMEM_QKV);
    cudaFuncSetAttribute(gemm_out, cudaFuncAttributeMaxDynamicSharedMemorySize, SMEM_GEMM1);
    cudaFuncSetAttribute(attn_mma, cudaFuncAttributeMaxDynamicSharedMemorySize, SMEM_ATT);

    mask_prep<<<32, 256>>>(mask);
    prep_round_x<<<MT * Dn / 4 / 256, 256>>>((const float4*)q);
    prep_round_w<<<dim3(Dn * Dn / 4 / 256, 4), 256>>>(
        (const float4*)Wq, (const float4*)Wk, (const float4*)Wv, (const float4*)Wo);

    gemm_qkv<<<dim3(Dn / 128, MT / 256, 3), 256, SMEM_QKV>>>();

    attn_mma<<<dim3(Hn, Nn / 128, Bn), 256, SMEM_ATT>>>(bias);

    gemm_out<<<dim3(Dn / 128, MT / 256, 1), 256, SMEM_GEMM1>>>(out);
}